// round 11
// baseline (speedup 1.0000x reference)
#include <cuda_runtime.h>
#include <math.h>
#include <stdint.h>

#define NB      64
#define NC      640      // K of all GEMMs
#define HW      784      // 28*28
#define S2      196      // 14*14
#define NHEADS  8
#define DH      64
#define INNER   512      // NHEADS*DH
#define EPSF    1e-5f
#define ATTN_SCALE 0.125f

// ---------------- scratch (device globals; no allocation) ----------------
__device__ float g_dwq [NB * NC * HW];       // dwconv(s1)+BN (tf32-rounded)
__device__ float g_dwkv[NB * NC * S2];       // dwconv(s2)+BN (tf32-rounded)
__device__ float g_q   [NB * INNER * HW];    // q  [b][h*64+d][pos], tf32
__device__ float g_kv  [NB * 2 * INNER * S2];// tf32
__device__ float g_res [NB * DH * HW];       // residual [b][d][pos], fp32
// fragment-major weight blobs: [mb][kt(20)][wr(4)][s(4)][mt(2)][lane(32)] float4
__device__ float g_wq  [NC * 512];           // q   blob: MB=4
__device__ float g_wkv [NC * 1024];          // kv  blob: MB=8
__device__ float g_wds [NC * 128];           // ds  blob: MB=1 (rows >=64 zero)

// ---------------- helpers ----------------
__device__ __forceinline__ float to_tf32(float v) {
    uint32_t r;
    asm("cvt.rna.tf32.f32 %0, %1;" : "=r"(r) : "f"(v));
    return __uint_as_float(r);
}

__device__ __forceinline__ void cp16(uint32_t dst, const void* src, int src_bytes) {
    asm volatile("cp.async.cg.shared.global [%0], [%1], 16, %2;\n"
                 :: "r"(dst), "l"(src), "r"(src_bytes));
}

__device__ __forceinline__ void mma_tf32(float* c, const uint32_t* a, const uint32_t* b) {
    asm volatile(
        "mma.sync.aligned.m16n8k8.row.col.f32.tf32.tf32.f32 "
        "{%0,%1,%2,%3}, {%4,%5,%6,%7}, {%8,%9}, {%0,%1,%2,%3};\n"
        : "+f"(c[0]), "+f"(c[1]), "+f"(c[2]), "+f"(c[3])
        : "r"(a[0]), "r"(a[1]), "r"(a[2]), "r"(a[3]), "r"(b[0]), "r"(b[1]));
}

// =====================================================================
// prep: build fragment-major weight blobs (one float4 entry per thread).
// entry e -> lane,mt,s,wr,kt,mb ; value A-fragment:
//   kq = kt*32 + s*8 + tig ; m = mb*128 + wr*32 + gid + mt*16
//   f4 = { W[kq][m], W[kq][m+8], W[kq+4][m], W[kq+4][m+8] },  W[k][m]=src[m*NC+k]
// =====================================================================
#define PREP_Q_E   81920    // 4 mb * 20 kt * 1024
#define PREP_KV_E  163840   // 8 mb
#define PREP_DS_E  20480    // 1 mb
__global__ void __launch_bounds__(256)
prep_all(const float* __restrict__ wq, const float* __restrict__ wkv,
         const float* __restrict__ wds)
{
    int e = blockIdx.x * 256 + threadIdx.x;
    const float* src;
    float4* dst;
    int Msrc, eloc;
    if (e < PREP_Q_E) {
        src = wq;  dst = (float4*)g_wq;  Msrc = 512;  eloc = e;
    } else if (e < PREP_Q_E + PREP_KV_E) {
        src = wkv; dst = (float4*)g_wkv; Msrc = 1024; eloc = e - PREP_Q_E;
    } else if (e < PREP_Q_E + PREP_KV_E + PREP_DS_E) {
        src = wds; dst = (float4*)g_wds; Msrc = 64;   eloc = e - PREP_Q_E - PREP_KV_E;
    } else return;

    const int lane = eloc & 31;
    const int mt   = (eloc >> 5) & 1;
    const int s    = (eloc >> 6) & 3;
    const int wr   = (eloc >> 8) & 3;
    const int rem  = eloc >> 10;
    const int kt   = rem % 20;
    const int mb   = rem / 20;
    const int tig  = lane & 3, gid = lane >> 2;
    const int kq   = kt * 32 + s * 8 + tig;
    const int m    = mb * 128 + wr * 32 + gid + mt * 16;

    float4 f;
    f.x = (m     < Msrc) ? to_tf32(src[(size_t)m       * NC + kq    ]) : 0.f;
    f.y = (m + 8 < Msrc) ? to_tf32(src[(size_t)(m + 8) * NC + kq    ]) : 0.f;
    f.z = (m     < Msrc) ? to_tf32(src[(size_t)m       * NC + kq + 4]) : 0.f;
    f.w = (m + 8 < Msrc) ? to_tf32(src[(size_t)(m + 8) * NC + kq + 4]) : 0.f;
    dst[eloc] = f;
}

// =====================================================================
// Fused depthwise conv (stride1 + stride2) + BN, per (b,c) block.
// =====================================================================
__global__ void __launch_bounds__(256)
dwconv_fused(const float* __restrict__ x,
             const float* __restrict__ wq, const float* __restrict__ wkv,
             const float* __restrict__ qg, const float* __restrict__ qb,
             const float* __restrict__ qm, const float* __restrict__ qvv,
             const float* __restrict__ kg, const float* __restrict__ kb,
             const float* __restrict__ km, const float* __restrict__ kvv)
{
    const int bc = blockIdx.x;
    const int c  = bc % NC;
    __shared__ float xs[30 * 30];
    const int tid = threadIdx.x;
    const int cx = tid & 31, ry = tid >> 5;

    for (int i = tid; i < 900; i += 256) xs[i] = 0.f;
    __syncthreads();
    const float* xp = x + (size_t)bc * HW;
    if (cx < 28) {
        for (int r = ry; r < 28; r += 8)
            xs[(r + 1) * 30 + cx + 1] = xp[r * 28 + cx];
    }
    __syncthreads();

    float wq9[9], wk9[9];
#pragma unroll
    for (int i = 0; i < 9; i++) { wq9[i] = wq[c * 9 + i]; wk9[i] = wkv[c * 9 + i]; }

    const float sq  = qg[c] * rsqrtf(qvv[c] + EPSF);
    const float bq  = qb[c] - qm[c] * sq;
    const float skv = kg[c] * rsqrtf(kvv[c] + EPSF);
    const float bkv = kb[c] - km[c] * skv;

    if (cx < 28) {
        float* oq = g_dwq + (size_t)bc * HW;
        for (int r = ry; r < 28; r += 8) {
            const float* s = &xs[r * 30 + cx];
            float acc = s[0]*wq9[0] + s[1]*wq9[1] + s[2]*wq9[2]
                      + s[30]*wq9[3] + s[31]*wq9[4] + s[32]*wq9[5]
                      + s[60]*wq9[6] + s[61]*wq9[7] + s[62]*wq9[8];
            oq[r * 28 + cx] = to_tf32(acc * sq + bq);
        }
    }
    if (cx < 14) {
        float* okv = g_dwkv + (size_t)bc * S2;
        for (int r = ry; r < 14; r += 8) {
            const float* s = &xs[(r * 2) * 30 + cx * 2];
            float acc = s[0]*wk9[0] + s[1]*wk9[1] + s[2]*wk9[2]
                      + s[30]*wk9[3] + s[31]*wk9[4] + s[32]*wk9[5]
                      + s[60]*wk9[6] + s[61]*wk9[7] + s[62]*wk9[8];
            okv[r * 14 + cx] = to_tf32(acc * skv + bkv);
        }
    }
}

// =====================================================================
// tf32 tensor-core GEMM, 128x64x32, fragment-major A (LDS.128 frags).
// A smem/stage: 4096 floats (blob copy), B smem/stage: 32x72.
// =====================================================================
#define A_STG 4096                       // floats per A stage
#define B_STG (32 * 72)                  // floats per B stage
#define STG   (A_STG + B_STG)            // 6400 floats
#define GEMM_SMEM_FLOATS (2 * STG)       // 51200 B
__global__ void __launch_bounds__(256)
gemm_tc(const float* __restrict__ wF, const float* __restrict__ act,
        float* __restrict__ Cc, int M, int N, int round_out,
        const float* __restrict__ bg, const float* __restrict__ bb,
        const float* __restrict__ bm, const float* __restrict__ bv)
{
    extern __shared__ float sm[];
    const int tid  = threadIdx.x;
    const int lane = tid & 31, warp = tid >> 5;
    const int wr   = warp >> 1;          // warp row 0..3
    const int wm   = wr * 32;
    const int wn   = (warp & 1) * 32;
    const int n0 = blockIdx.x * 64;
    const int m0 = blockIdx.y * 128;
    const float* Ab = act + (size_t)blockIdx.z * NC * N;
    float*       Cb = Cc  + (size_t)blockIdx.z * (size_t)M * N;
    const float* blob = wF + (size_t)blockIdx.y * 20 * A_STG;

    float acc[2][4][4];
#pragma unroll
    for (int i = 0; i < 2; i++)
#pragma unroll
        for (int j = 0; j < 4; j++)
#pragma unroll
            for (int l = 0; l < 4; l++) acc[i][j][l] = 0.f;

    const int b_k = tid >> 4, b_n4 = (tid & 15) << 2;

    auto load_tile = [&](int kt, int st) {
        float* As = sm + st * STG;
        float* Bs = As + A_STG;
        // A: contiguous 16KB blob for this k-tile
        {
            const float* srcA = blob + (size_t)kt * A_STG + tid * 16;
            uint32_t dstA = (uint32_t)__cvta_generic_to_shared(&As[tid * 16]);
            cp16(dstA,      srcA,      16);
            cp16(dstA + 16, srcA + 4,  16);
            cp16(dstA + 32, srcA + 8,  16);
            cp16(dstA + 48, srcA + 12, 16);
        }
        // B: rows kt*32 .. +31, cols n0..n0+63 (guard vs N)
#pragma unroll
        for (int i = 0; i < 2; i++) {
            int k = b_k + i * 16;
            int col = n0 + b_n4;
            uint32_t dst = (uint32_t)__cvta_generic_to_shared(&Bs[k * 72 + b_n4]);
            cp16(dst, Ab + (size_t)(kt * 32 + k) * N + col, (col < N) ? 16 : 0);
        }
        asm volatile("cp.async.commit_group;\n");
    };

    load_tile(0, 0);
    for (int t = 0; t < 20; t++) {
        const int st = t & 1;
        if (t < 19) {
            load_tile(t + 1, st ^ 1);
            asm volatile("cp.async.wait_group 1;\n");
        } else {
            asm volatile("cp.async.wait_group 0;\n");
        }
        __syncthreads();
        const float4* As4 = (const float4*)(sm + st * STG);
        const float*  Bs  = sm + st * STG + A_STG;
#pragma unroll
        for (int sidx = 0; sidx < 4; sidx++) {
            const int kq   = sidx * 8 + (lane & 3);
            const int ncol = wn + (lane >> 2);
            float4 afv[2];
            afv[0] = As4[((wr * 4 + sidx) * 2 + 0) * 32 + lane];
            afv[1] = As4[((wr * 4 + sidx) * 2 + 1) * 32 + lane];
            uint32_t bf[4][2];
#pragma unroll
            for (int nt = 0; nt < 4; nt++) {
                bf[nt][0] = __float_as_uint(Bs[kq * 72 + ncol + nt * 8]);
                bf[nt][1] = __float_as_uint(Bs[(kq + 4) * 72 + ncol + nt * 8]);
            }
#pragma unroll
            for (int mt = 0; mt < 2; mt++) {
                uint32_t af[4];
                af[0] = __float_as_uint(afv[mt].x);
                af[1] = __float_as_uint(afv[mt].y);
                af[2] = __float_as_uint(afv[mt].z);
                af[3] = __float_as_uint(afv[mt].w);
#pragma unroll
                for (int nt = 0; nt < 4; nt++)
                    mma_tf32(acc[mt][nt], af, bf[nt]);
            }
        }
        __syncthreads();
    }

    const bool has_bn = (bg != nullptr);
#pragma unroll
    for (int mt = 0; mt < 2; mt++) {
#pragma unroll
        for (int half = 0; half < 2; half++) {
            const int m = m0 + wm + mt * 16 + (lane >> 2) + half * 8;
            if (m >= M) continue;
            float sc = 1.f, bi = 0.f;
            if (has_bn) { sc = bg[m] * rsqrtf(bv[m] + EPSF); bi = bb[m] - bm[m] * sc; }
#pragma unroll
            for (int nt = 0; nt < 4; nt++) {
                const int n = n0 + wn + nt * 8 + 2 * (lane & 3);
                if (n < N) {
                    float2 v;
                    v.x = acc[mt][nt][half * 2 + 0] * sc + bi;
                    v.y = acc[mt][nt][half * 2 + 1] * sc + bi;
                    if (round_out) { v.x = to_tf32(v.x); v.y = to_tf32(v.y); }
                    *(float2*)&Cb[(size_t)m * N + n] = v;
                }
            }
        }
    }
}

// =====================================================================
// Tensor-core attention (R8 version): register softmax, K/V [200][68].
// =====================================================================
__global__ void __launch_bounds__(256)
attn_tc(const float* __restrict__ lnw, const float* __restrict__ lnbp,
        float* __restrict__ out)
{
    const int bh = blockIdx.x;
    const int b  = bh >> 3;
    const int h  = bh & 7;

    extern __shared__ __align__(16) float sm[];
    float* ksm  = sm;                    // [200][68]
    float* vsm  = ksm + 200 * 68;        // [200][68]
    float* pool = vsm + 200 * 68;        // [8][64]
    float* lnsm = pool + 512;            // gamma[64], beta[64]

    const int tid  = threadIdx.x;
    const int lane = tid & 31, warp = tid >> 5;
    const int gid  = lane >> 2, tig = lane & 3;

    const float* kg = g_kv + ((size_t)b * 1024 + h * 64) * S2;
    const float* vg = g_kv + ((size_t)b * 1024 + 512 + h * 64) * S2;
    for (int idx = tid; idx < 200 * 64; idx += 256) {
        int j = idx % 200, d = idx / 200;
        ksm[j * 68 + d] = (j < S2) ? kg[(size_t)d * S2 + j] : 0.f;
        vsm[j * 68 + d] = (j < S2) ? vg[(size_t)d * S2 + j] : 0.f;
    }
    if (tid < 128) lnsm[tid] = (tid < 64) ? lnw[h * 64 + tid] : lnbp[h * 64 + tid - 64];
    __syncthreads();

    float pacc[16];
#pragma unroll
    for (int i = 0; i < 16; i++) pacc[i] = 0.f;

    const float* qg = g_q + ((size_t)b * INNER + h * 64) * HW;
    const float* rg = g_res + (size_t)b * DH * HW;

    const int srcLow  = (lane & ~3) | (tig >> 1);
    const int srcHigh = srcLow + 2;
    const bool odd = (tig & 1) != 0;

    for (int t = warp; t < 49; t += 8) {
        const int r0 = t * 16;

        float sacc[25][4];
#pragma unroll
        for (int nt = 0; nt < 25; nt++) {
            sacc[nt][0] = sacc[nt][1] = sacc[nt][2] = sacc[nt][3] = 0.f;
        }
#pragma unroll
        for (int kk = 0; kk < 8; kk++) {
            const int d0 = kk * 8 + tig;
            uint32_t a[4];
            a[0] = __float_as_uint(qg[(size_t)d0 * HW + r0 + gid]);
            a[1] = __float_as_uint(qg[(size_t)d0 * HW + r0 + gid + 8]);
            a[2] = __float_as_uint(qg[(size_t)(d0 + 4) * HW + r0 + gid]);
            a[3] = __float_as_uint(qg[(size_t)(d0 + 4) * HW + r0 + gid + 8]);
#pragma unroll
            for (int nt = 0; nt < 25; nt++) {
                uint32_t bfr[2];
                bfr[0] = __float_as_uint(ksm[(nt * 8 + gid) * 68 + d0]);
                bfr[1] = __float_as_uint(ksm[(nt * 8 + gid) * 68 + d0 + 4]);
                mma_tf32(sacc[nt], a, bfr);
            }
        }
        if (tig >= 2) {
            sacc[24][0] = sacc[24][1] = sacc[24][2] = sacc[24][3] = -1e30f;
        }

        float mlo = -1e30f, mhi = -1e30f;
#pragma unroll
        for (int nt = 0; nt < 25; nt++) {
            mlo = fmaxf(mlo, fmaxf(sacc[nt][0], sacc[nt][1]));
            mhi = fmaxf(mhi, fmaxf(sacc[nt][2], sacc[nt][3]));
        }
        mlo = fmaxf(mlo, __shfl_xor_sync(0xffffffffu, mlo, 1));
        mlo = fmaxf(mlo, __shfl_xor_sync(0xffffffffu, mlo, 2));
        mhi = fmaxf(mhi, __shfl_xor_sync(0xffffffffu, mhi, 1));
        mhi = fmaxf(mhi, __shfl_xor_sync(0xffffffffu, mhi, 2));
        const float mls = mlo * ATTN_SCALE, mhs = mhi * ATTN_SCALE;
        float slo = 0.f, shi = 0.f;
#pragma unroll
        for (int nt = 0; nt < 25; nt++) {
            float e0 = __expf(fmaf(sacc[nt][0], ATTN_SCALE, -mls));
            float e1 = __expf(fmaf(sacc[nt][1], ATTN_SCALE, -mls));
            float e2 = __expf(fmaf(sacc[nt][2], ATTN_SCALE, -mhs));
            float e3 = __expf(fmaf(sacc[nt][3], ATTN_SCALE, -mhs));
            sacc[nt][0] = e0; sacc[nt][1] = e1; sacc[nt][2] = e2; sacc[nt][3] = e3;
            slo += e0 + e1; shi += e2 + e3;
        }
        slo += __shfl_xor_sync(0xffffffffu, slo, 1);
        slo += __shfl_xor_sync(0xffffffffu, slo, 2);
        shi += __shfl_xor_sync(0xffffffffu, shi, 1);
        shi += __shfl_xor_sync(0xffffffffu, shi, 2);
        const float rlo = 1.f / slo, rhi = 1.f / shi;
#pragma unroll
        for (int nt = 0; nt < 25; nt++) {
            sacc[nt][0] *= rlo; sacc[nt][1] *= rlo;
            sacc[nt][2] *= rhi; sacc[nt][3] *= rhi;
        }

        float oacc[8][4];
#pragma unroll
        for (int nt = 0; nt < 8; nt++) {
            oacc[nt][0] = oacc[nt][1] = oacc[nt][2] = oacc[nt][3] = 0.f;
        }
#pragma unroll
        for (int kk = 0; kk < 25; kk++) {
            float u0 = __shfl_sync(0xffffffffu, sacc[kk][0], srcLow);
            float u1 = __shfl_sync(0xffffffffu, sacc[kk][1], srcLow);
            float w0 = __shfl_sync(0xffffffffu, sacc[kk][2], srcLow);
            float w1 = __shfl_sync(0xffffffffu, sacc[kk][3], srcLow);
            float v0 = __shfl_sync(0xffffffffu, sacc[kk][0], srcHigh);
            float v1 = __shfl_sync(0xffffffffu, sacc[kk][1], srcHigh);
            float z0 = __shfl_sync(0xffffffffu, sacc[kk][2], srcHigh);
            float z1 = __shfl_sync(0xffffffffu, sacc[kk][3], srcHigh);
            uint32_t a[4];
            a[0] = __float_as_uint(odd ? u1 : u0);
            a[1] = __float_as_uint(odd ? w1 : w0);
            a[2] = __float_as_uint(odd ? v1 : v0);
            a[3] = __float_as_uint(odd ? z1 : z0);
            const int j0 = kk * 8 + tig;
#pragma unroll
            for (int nt = 0; nt < 8; nt++) {
                uint32_t bfr[2];
                bfr[0] = __float_as_uint(vsm[j0 * 68 + nt * 8 + gid]);
                bfr[1] = __float_as_uint(vsm[(j0 + 4) * 68 + nt * 8 + gid]);
                mma_tf32(oacc[nt], a, bfr);
            }
        }

        float vlo[16], vhi[16];
        float slo2 = 0.f, shi2 = 0.f;
#pragma unroll
        for (int nt = 0; nt < 8; nt++)
#pragma unroll
            for (int c = 0; c < 2; c++) {
                const int i = nt * 2 + c;
                const int d = nt * 8 + 2 * tig + c;
                vlo[i] = oacc[nt][c]     + rg[(size_t)d * HW + r0 + gid];
                vhi[i] = oacc[nt][2 + c] + rg[(size_t)d * HW + r0 + gid + 8];
                slo2 += vlo[i]; shi2 += vhi[i];
            }
        slo2 += __shfl_xor_sync(0xffffffffu, slo2, 1);
        slo2 += __shfl_xor_sync(0xffffffffu, slo2, 2);
        shi2 += __shfl_xor_sync(0xffffffffu, shi2, 1);
        shi2 += __shfl_xor_sync(0xffffffffu, shi2, 2);
        const float mlo2 = slo2 * (1.f / 64.f), mhi2 = shi2 * (1.f / 64.f);
        float qlo = 0.f, qhi = 0.f;
#pragma unroll
        for (int i = 0; i < 16; i++) {
            float t1 = vlo[i] - mlo2; qlo += t1 * t1;
            float t2 = vhi[i] - mhi2; qhi += t2 * t2;
        }
        qlo += __shfl_xor_sync(0xffffffffu, qlo, 1);
        qlo += __shfl_xor_sync(0xffffffffu, qlo, 2);
        qhi += __shfl_xor_sync(0xffffffffu, qhi, 1);
        qhi += __shfl_xor_sync(0xffffffffu, qhi, 2);
        const float ilo = 1.f / (sqrtf(qlo * (1.f / 64.f)) + EPSF);
        const float ihi = 1.f / (sqrtf(qhi * (1.f / 64.f)) + EPSF);
#pragma unroll
        for (int nt = 0; nt < 8; nt++)
#pragma unroll
            for (int c = 0; c < 2; c++) {
                const int i = nt * 2 + c;
                const int d = nt * 8 + 2 * tig + c;
                const float lg = lnsm[d], lb = lnsm[64 + d];
                pacc[i] += (vlo[i] - mlo2) * ilo * lg + lb
                         + (vhi[i] - mhi2) * ihi * lg + lb;
            }
    }

#pragma unroll
    for (int i = 0; i < 16; i++) {
        pacc[i] += __shfl_xor_sync(0xffffffffu, pacc[i], 4);
        pacc[i] += __shfl_xor_sync(0xffffffffu, pacc[i], 8);
        pacc[i] += __shfl_xor_sync(0xffffffffu, pacc[i], 16);
    }
    if (gid == 0) {
#pragma unroll
        for (int nt = 0; nt < 8; nt++)
#pragma unroll
            for (int c = 0; c < 2; c++) {
                const int d = nt * 8 + 2 * tig + c;
                pool[warp * 64 + d] = pacc[nt * 2 + c];
            }
    }
    __syncthreads();
    if (tid < 64) {
        float s = 0.f;
#pragma unroll
        for (int w = 0; w < 8; w++) s += pool[w * 64 + tid];
        out[(size_t)bh * 64 + tid] = s * (1.f / 784.f);
    }
}

// =====================================================================
extern "C" void kernel_launch(void* const* d_in, const int* in_sizes, int n_in,
                              void* d_out, int out_size)
{
    const float* x      = (const float*)d_in[0];
    const float* w_dwq  = (const float*)d_in[1];
    const float* w_pwq  = (const float*)d_in[2];
    const float* w_dwkv = (const float*)d_in[3];
    const float* w_pwkv = (const float*)d_in[4];
    const float* w_ds   = (const float*)d_in[5];
    const float* ln_g   = (const float*)d_in[6];
    const float* ln_b   = (const float*)d_in[7];
    const float* bnq_g  = (const float*)d_in[8];
    const float* bnq_b  = (const float*)d_in[9];
    const float* bnq_m  = (const float*)d_in[10];
    const float* bnq_v  = (const float*)d_in[11];
    const float* bnkv_g = (const float*)d_in[12];
    const float* bnkv_b = (const float*)d_in[13];
    const float* bnkv_m = (const float*)d_in[14];
    const float* bnkv_v = (const float*)d_in[15];
    const float* bnds_g = (const float*)d_in[16];
    const float* bnds_b = (const float*)d_in[17];
    const float* bnds_m = (const float*)d_in[18];
    const float* bnds_v = (const float*)d_in[19];
    float* out = (float*)d_out;

    float *p_dwq, *p_dwkv, *p_q, *p_kv, *p_res, *p_wq, *p_wkv, *p_wds;
    cudaGetSymbolAddress((void**)&p_dwq,  g_dwq);
    cudaGetSymbolAddress((void**)&p_dwkv, g_dwkv);
    cudaGetSymbolAddress((void**)&p_q,    g_q);
    cudaGetSymbolAddress((void**)&p_kv,   g_kv);
    cudaGetSymbolAddress((void**)&p_res,  g_res);
    cudaGetSymbolAddress((void**)&p_wq,   g_wq);
    cudaGetSymbolAddress((void**)&p_wkv,  g_wkv);
    cudaGetSymbolAddress((void**)&p_wds,  g_wds);

    const int attn_smem = (2 * 200 * 68 + 512 + 128) * (int)sizeof(float); // 111360
    const int gemm_smem = GEMM_SMEM_FLOATS * (int)sizeof(float);           // 51200
    static bool attr_done = false;
    if (!attr_done) {
        cudaFuncSetAttribute(attn_tc,
                             cudaFuncAttributeMaxDynamicSharedMemorySize, attn_smem);
        cudaFuncSetAttribute(gemm_tc,
                             cudaFuncAttributeMaxDynamicSharedMemorySize, gemm_smem);
        attr_done = true;
    }

    // 0) weight prep: fragment-major tf32 blobs
    const int prep_total = PREP_Q_E + PREP_KV_E + PREP_DS_E;
    prep_all<<<(prep_total + 255) / 256, 256>>>(w_pwq, w_pwkv, w_ds);

    // 1) fused depthwise convs + BN
    dwconv_fused<<<NB * NC, 256>>>(x, w_dwq, w_dwkv,
                                   bnq_g, bnq_b, bnq_m, bnq_v,
                                   bnkv_g, bnkv_b, bnkv_m, bnkv_v);

    // 2) residual pointwise conv + BN (fp32 output)
    gemm_tc<<<dim3(13, 1, NB), 256, gemm_smem>>>(p_wds, x, p_res, DH, HW, 0,
                                                 bnds_g, bnds_b, bnds_m, bnds_v);

    // 3) q projection (tf32-rounded output)
    gemm_tc<<<dim3(13, 4, NB), 256, gemm_smem>>>(p_wq, p_dwq, p_q, INNER, HW, 1,
                                                 nullptr, nullptr, nullptr, nullptr);

    // 4) kv projection (tf32-rounded output)
    gemm_tc<<<dim3(4, 8, NB), 256, gemm_smem>>>(p_wkv, p_dwkv, p_kv, 2 * INNER, S2, 1,
                                                nullptr, nullptr, nullptr, nullptr);

    // 5) tensor-core attention + residual + LN + mean pool
    attn_tc<<<NB * NHEADS, 256, attn_smem>>>(ln_g, ln_b, out);
}

// round 12
// speedup vs baseline: 1.1020x; 1.1020x over previous
#include <cuda_runtime.h>
#include <math.h>
#include <stdint.h>

#define NB      64
#define NC      640      // K of all GEMMs
#define HW      784      // 28*28
#define S2      196      // 14*14
#define NHEADS  8
#define DH      64
#define INNER   512      // NHEADS*DH
#define EPSF    1e-5f
#define ATTN_SCALE 0.125f

// ---------------- scratch (device globals; no allocation) ----------------
__device__ float g_dwq [NB * NC * HW];       // dwconv(s1)+BN (tf32-rounded)
__device__ float g_dwkv[NB * NC * S2];       // dwconv(s2)+BN (tf32-rounded)
__device__ float g_q   [NB * INNER * HW];    // q  [b][h*64+d][pos], tf32
__device__ float g_kv  [NB * 2 * INNER * S2];// tf32
__device__ float g_res [NB * DH * HW];       // residual [b][d][pos], fp32
__device__ float g_wq  [NC * 512];           // w_pwq^T  [k][m], tf32
__device__ float g_wkv [NC * 1024];          // w_pwkv^T [k][m], tf32
__device__ float g_wds [NC * 128];           // w_ds^T   [k][m], tf32, zero-padded to 128

// ---------------- helpers ----------------
__device__ __forceinline__ float to_tf32(float v) {
    uint32_t r;
    asm("cvt.rna.tf32.f32 %0, %1;" : "=r"(r) : "f"(v));
    return __uint_as_float(r);
}

__device__ __forceinline__ void cp16(uint32_t dst, const void* src, int src_bytes) {
    asm volatile("cp.async.cg.shared.global [%0], [%1], 16, %2;\n"
                 :: "r"(dst), "l"(src), "r"(src_bytes));
}

__device__ __forceinline__ void mma_tf32(float* c, const uint32_t* a, const uint32_t* b) {
    asm volatile(
        "mma.sync.aligned.m16n8k8.row.col.f32.tf32.tf32.f32 "
        "{%0,%1,%2,%3}, {%4,%5,%6,%7}, {%8,%9}, {%0,%1,%2,%3};\n"
        : "+f"(c[0]), "+f"(c[1]), "+f"(c[2]), "+f"(c[3])
        : "r"(a[0]), "r"(a[1]), "r"(a[2]), "r"(a[3]), "r"(b[0]), "r"(b[1]));
}

// =====================================================================
// Single prep kernel: transpose + tf32-round all three weight matrices.
// =====================================================================
#define PREP_Q_SZ   (NC * 512)
#define PREP_KV_SZ  (NC * 1024)
#define PREP_DS_SZ  (NC * 128)
__global__ void __launch_bounds__(256)
prep_all(const float* __restrict__ wq, const float* __restrict__ wkv,
         const float* __restrict__ wds)
{
    int idx = blockIdx.x * 256 + threadIdx.x;
    if (idx < PREP_Q_SZ) {
        int k = idx / 512, m = idx - k * 512;
        g_wq[idx] = to_tf32(wq[(size_t)m * NC + k]);
    } else if (idx < PREP_Q_SZ + PREP_KV_SZ) {
        int i = idx - PREP_Q_SZ;
        int k = i / 1024, m = i - k * 1024;
        g_wkv[i] = to_tf32(wkv[(size_t)m * NC + k]);
    } else if (idx < PREP_Q_SZ + PREP_KV_SZ + PREP_DS_SZ) {
        int i = idx - PREP_Q_SZ - PREP_KV_SZ;
        int k = i / 128, m = i - k * 128;
        g_wds[i] = (m < 64) ? to_tf32(wds[(size_t)m * NC + k]) : 0.f;
    }
}

// =====================================================================
// Fused depthwise conv (stride1 + stride2) + BN, per (b,c) block.
// =====================================================================
__global__ void __launch_bounds__(256)
dwconv_fused(const float* __restrict__ x,
             const float* __restrict__ wq, const float* __restrict__ wkv,
             const float* __restrict__ qg, const float* __restrict__ qb,
             const float* __restrict__ qm, const float* __restrict__ qvv,
             const float* __restrict__ kg, const float* __restrict__ kb,
             const float* __restrict__ km, const float* __restrict__ kvv)
{
    const int bc = blockIdx.x;
    const int c  = bc % NC;
    __shared__ float xs[30 * 30];
    const int tid = threadIdx.x;
    const int cx = tid & 31, ry = tid >> 5;

    for (int i = tid; i < 900; i += 256) xs[i] = 0.f;
    __syncthreads();
    const float* xp = x + (size_t)bc * HW;
    if (cx < 28) {
        for (int r = ry; r < 28; r += 8)
            xs[(r + 1) * 30 + cx + 1] = xp[r * 28 + cx];
    }
    __syncthreads();

    float wq9[9], wk9[9];
#pragma unroll
    for (int i = 0; i < 9; i++) { wq9[i] = wq[c * 9 + i]; wk9[i] = wkv[c * 9 + i]; }

    const float sq  = qg[c] * rsqrtf(qvv[c] + EPSF);
    const float bq  = qb[c] - qm[c] * sq;
    const float skv = kg[c] * rsqrtf(kvv[c] + EPSF);
    const float bkv = kb[c] - km[c] * skv;

    if (cx < 28) {
        float* oq = g_dwq + (size_t)bc * HW;
        for (int r = ry; r < 28; r += 8) {
            const float* s = &xs[r * 30 + cx];
            float acc = s[0]*wq9[0] + s[1]*wq9[1] + s[2]*wq9[2]
                      + s[30]*wq9[3] + s[31]*wq9[4] + s[32]*wq9[5]
                      + s[60]*wq9[6] + s[61]*wq9[7] + s[62]*wq9[8];
            oq[r * 28 + cx] = to_tf32(acc * sq + bq);
        }
    }
    if (cx < 14) {
        float* okv = g_dwkv + (size_t)bc * S2;
        for (int r = ry; r < 14; r += 8) {
            const float* s = &xs[(r * 2) * 30 + cx * 2];
            float acc = s[0]*wk9[0] + s[1]*wk9[1] + s[2]*wk9[2]
                      + s[30]*wk9[3] + s[31]*wk9[4] + s[32]*wk9[5]
                      + s[60]*wk9[6] + s[61]*wk9[7] + s[62]*wk9[8];
            okv[r * 14 + cx] = to_tf32(acc * skv + bkv);
        }
    }
}

// =====================================================================
// tf32 tensor-core GEMM (R8 config: 128x64x32, 4 blocks/SM)
// =====================================================================
#define GEMM_SMEM_FLOATS (2 * (32 * 136 + 32 * 72))
__global__ void __launch_bounds__(256)
gemm_tc(const float* __restrict__ wT, const float* __restrict__ act,
        float* __restrict__ Cc, int Mpad, int M, int N, int round_out,
        const float* __restrict__ bg, const float* __restrict__ bb,
        const float* __restrict__ bm, const float* __restrict__ bv)
{
    extern __shared__ float sm[];
    const int tid  = threadIdx.x;
    const int lane = tid & 31, warp = tid >> 5;
    const int wm = (warp >> 1) * 32;
    const int wn = (warp & 1) * 32;
    const int n0 = blockIdx.x * 64;
    const int m0 = blockIdx.y * 128;
    const float* Ab = act + (size_t)blockIdx.z * NC * N;
    float*       Cb = Cc  + (size_t)blockIdx.z * (size_t)M * N;

    float acc[2][4][4];
#pragma unroll
    for (int i = 0; i < 2; i++)
#pragma unroll
        for (int j = 0; j < 4; j++)
#pragma unroll
            for (int l = 0; l < 4; l++) acc[i][j][l] = 0.f;

    const int a_k = tid >> 5, a_m4 = (tid & 31) * 4;
    const int b_k = tid >> 4, b_n4 = (tid & 15) * 4;

    auto load_tile = [&](int k0, int st) {
        float* As = sm + st * (32 * 136 + 32 * 72);
        float* Bs = As + 32 * 136;
#pragma unroll
        for (int i = 0; i < 4; i++) {
            int k = a_k + i * 8;
            uint32_t dst = (uint32_t)__cvta_generic_to_shared(&As[k * 136 + a_m4]);
            cp16(dst, wT + (size_t)(k0 + k) * Mpad + m0 + a_m4, 16);
        }
#pragma unroll
        for (int i = 0; i < 2; i++) {
            int k = b_k + i * 16;
            int col = n0 + b_n4;
            uint32_t dst = (uint32_t)__cvta_generic_to_shared(&Bs[k * 72 + b_n4]);
            cp16(dst, Ab + (size_t)(k0 + k) * N + col, (col < N) ? 16 : 0);
        }
        asm volatile("cp.async.commit_group;\n");
    };

    load_tile(0, 0);
    for (int t = 0; t < 20; t++) {
        const int st = t & 1;
        if (t < 19) {
            load_tile((t + 1) * 32, st ^ 1);
            asm volatile("cp.async.wait_group 1;\n");
        } else {
            asm volatile("cp.async.wait_group 0;\n");
        }
        __syncthreads();
        const float* As = sm + st * (32 * 136 + 32 * 72);
        const float* Bs = As + 32 * 136;
#pragma unroll
        for (int kk = 0; kk < 32; kk += 8) {
            uint32_t af[2][4], bf[4][2];
            const int kq   = kk + (lane & 3);
            const int mrow = wm + (lane >> 2);
            const int ncol = wn + (lane >> 2);
#pragma unroll
            for (int mt = 0; mt < 2; mt++) {
                af[mt][0] = __float_as_uint(As[kq * 136 + mrow + mt * 16]);
                af[mt][1] = __float_as_uint(As[kq * 136 + mrow + mt * 16 + 8]);
                af[mt][2] = __float_as_uint(As[(kq + 4) * 136 + mrow + mt * 16]);
                af[mt][3] = __float_as_uint(As[(kq + 4) * 136 + mrow + mt * 16 + 8]);
            }
#pragma unroll
            for (int nt = 0; nt < 4; nt++) {
                bf[nt][0] = __float_as_uint(Bs[kq * 72 + ncol + nt * 8]);
                bf[nt][1] = __float_as_uint(Bs[(kq + 4) * 72 + ncol + nt * 8]);
            }
#pragma unroll
            for (int mt = 0; mt < 2; mt++)
#pragma unroll
                for (int nt = 0; nt < 4; nt++)
                    mma_tf32(acc[mt][nt], af[mt], bf[nt]);
        }
        __syncthreads();
    }

    const bool has_bn = (bg != nullptr);
#pragma unroll
    for (int mt = 0; mt < 2; mt++) {
#pragma unroll
        for (int half = 0; half < 2; half++) {
            const int m = m0 + wm + mt * 16 + (lane >> 2) + half * 8;
            if (m >= M) continue;
            float sc = 1.f, bi = 0.f;
            if (has_bn) { sc = bg[m] * rsqrtf(bv[m] + EPSF); bi = bb[m] - bm[m] * sc; }
#pragma unroll
            for (int nt = 0; nt < 4; nt++) {
                const int n = n0 + wn + nt * 8 + 2 * (lane & 3);
                if (n < N) {
                    float2 v;
                    v.x = acc[mt][nt][half * 2 + 0] * sc + bi;
                    v.y = acc[mt][nt][half * 2 + 1] * sc + bi;
                    if (round_out) { v.x = to_tf32(v.x); v.y = to_tf32(v.y); }
                    *(float2*)&Cb[(size_t)m * N + n] = v;
                }
            }
        }
    }
}

// =====================================================================
// Tensor-core attention (R8 version): register softmax, K/V [200][68].
// =====================================================================
__global__ void __launch_bounds__(256)
attn_tc(const float* __restrict__ lnw, const float* __restrict__ lnbp,
        float* __restrict__ out)
{
    const int bh = blockIdx.x;
    const int b  = bh >> 3;
    const int h  = bh & 7;

    extern __shared__ __align__(16) float sm[];
    float* ksm  = sm;                    // [200][68]
    float* vsm  = ksm + 200 * 68;        // [200][68]
    float* pool = vsm + 200 * 68;        // [8][64]
    float* lnsm = pool + 512;            // gamma[64], beta[64]

    const int tid  = threadIdx.x;
    const int lane = tid & 31, warp = tid >> 5;
    const int gid  = lane >> 2, tig = lane & 3;

    const float* kg = g_kv + ((size_t)b * 1024 + h * 64) * S2;
    const float* vg = g_kv + ((size_t)b * 1024 + 512 + h * 64) * S2;
    for (int idx = tid; idx < 200 * 64; idx += 256) {
        int j = idx % 200, d = idx / 200;
        ksm[j * 68 + d] = (j < S2) ? kg[(size_t)d * S2 + j] : 0.f;
        vsm[j * 68 + d] = (j < S2) ? vg[(size_t)d * S2 + j] : 0.f;
    }
    if (tid < 128) lnsm[tid] = (tid < 64) ? lnw[h * 64 + tid] : lnbp[h * 64 + tid - 64];
    __syncthreads();

    float pacc[16];
#pragma unroll
    for (int i = 0; i < 16; i++) pacc[i] = 0.f;

    const float* qg = g_q + ((size_t)b * INNER + h * 64) * HW;
    const float* rg = g_res + (size_t)b * DH * HW;

    const int srcLow  = (lane & ~3) | (tig >> 1);
    const int srcHigh = srcLow + 2;
    const bool odd = (tig & 1) != 0;

    for (int t = warp; t < 49; t += 8) {
        const int r0 = t * 16;

        float sacc[25][4];
#pragma unroll
        for (int nt = 0; nt < 25; nt++) {
            sacc[nt][0] = sacc[nt][1] = sacc[nt][2] = sacc[nt][3] = 0.f;
        }
#pragma unroll
        for (int kk = 0; kk < 8; kk++) {
            const int d0 = kk * 8 + tig;
            uint32_t a[4];
            a[0] = __float_as_uint(qg[(size_t)d0 * HW + r0 + gid]);
            a[1] = __float_as_uint(qg[(size_t)d0 * HW + r0 + gid + 8]);
            a[2] = __float_as_uint(qg[(size_t)(d0 + 4) * HW + r0 + gid]);
            a[3] = __float_as_uint(qg[(size_t)(d0 + 4) * HW + r0 + gid + 8]);
#pragma unroll
            for (int nt = 0; nt < 25; nt++) {
                uint32_t bfr[2];
                bfr[0] = __float_as_uint(ksm[(nt * 8 + gid) * 68 + d0]);
                bfr[1] = __float_as_uint(ksm[(nt * 8 + gid) * 68 + d0 + 4]);
                mma_tf32(sacc[nt], a, bfr);
            }
        }
        if (tig >= 2) {
            sacc[24][0] = sacc[24][1] = sacc[24][2] = sacc[24][3] = -1e30f;
        }

        float mlo = -1e30f, mhi = -1e30f;
#pragma unroll
        for (int nt = 0; nt < 25; nt++) {
            mlo = fmaxf(mlo, fmaxf(sacc[nt][0], sacc[nt][1]));
            mhi = fmaxf(mhi, fmaxf(sacc[nt][2], sacc[nt][3]));
        }
        mlo = fmaxf(mlo, __shfl_xor_sync(0xffffffffu, mlo, 1));
        mlo = fmaxf(mlo, __shfl_xor_sync(0xffffffffu, mlo, 2));
        mhi = fmaxf(mhi, __shfl_xor_sync(0xffffffffu, mhi, 1));
        mhi = fmaxf(mhi, __shfl_xor_sync(0xffffffffu, mhi, 2));
        const float mls = mlo * ATTN_SCALE, mhs = mhi * ATTN_SCALE;
        float slo = 0.f, shi = 0.f;
#pragma unroll
        for (int nt = 0; nt < 25; nt++) {
            float e0 = __expf(fmaf(sacc[nt][0], ATTN_SCALE, -mls));
            float e1 = __expf(fmaf(sacc[nt][1], ATTN_SCALE, -mls));
            float e2 = __expf(fmaf(sacc[nt][2], ATTN_SCALE, -mhs));
            float e3 = __expf(fmaf(sacc[nt][3], ATTN_SCALE, -mhs));
            sacc[nt][0] = e0; sacc[nt][1] = e1; sacc[nt][2] = e2; sacc[nt][3] = e3;
            slo += e0 + e1; shi += e2 + e3;
        }
        slo += __shfl_xor_sync(0xffffffffu, slo, 1);
        slo += __shfl_xor_sync(0xffffffffu, slo, 2);
        shi += __shfl_xor_sync(0xffffffffu, shi, 1);
        shi += __shfl_xor_sync(0xffffffffu, shi, 2);
        const float rlo = 1.f / slo, rhi = 1.f / shi;
#pragma unroll
        for (int nt = 0; nt < 25; nt++) {
            sacc[nt][0] *= rlo; sacc[nt][1] *= rlo;
            sacc[nt][2] *= rhi; sacc[nt][3] *= rhi;
        }

        float oacc[8][4];
#pragma unroll
        for (int nt = 0; nt < 8; nt++) {
            oacc[nt][0] = oacc[nt][1] = oacc[nt][2] = oacc[nt][3] = 0.f;
        }
#pragma unroll
        for (int kk = 0; kk < 25; kk++) {
            float u0 = __shfl_sync(0xffffffffu, sacc[kk][0], srcLow);
            float u1 = __shfl_sync(0xffffffffu, sacc[kk][1], srcLow);
            float w0 = __shfl_sync(0xffffffffu, sacc[kk][2], srcLow);
            float w1 = __shfl_sync(0xffffffffu, sacc[kk][3], srcLow);
            float v0 = __shfl_sync(0xffffffffu, sacc[kk][0], srcHigh);
            float v1 = __shfl_sync(0xffffffffu, sacc[kk][1], srcHigh);
            float z0 = __shfl_sync(0xffffffffu, sacc[kk][2], srcHigh);
            float z1 = __shfl_sync(0xffffffffu, sacc[kk][3], srcHigh);
            uint32_t a[4];
            a[0] = __float_as_uint(odd ? u1 : u0);
            a[1] = __float_as_uint(odd ? w1 : w0);
            a[2] = __float_as_uint(odd ? v1 : v0);
            a[3] = __float_as_uint(odd ? z1 : z0);
            const int j0 = kk * 8 + tig;
#pragma unroll
            for (int nt = 0; nt < 8; nt++) {
                uint32_t bfr[2];
                bfr[0] = __float_as_uint(vsm[j0 * 68 + nt * 8 + gid]);
                bfr[1] = __float_as_uint(vsm[(j0 + 4) * 68 + nt * 8 + gid]);
                mma_tf32(oacc[nt], a, bfr);
            }
        }

        float vlo[16], vhi[16];
        float slo2 = 0.f, shi2 = 0.f;
#pragma unroll
        for (int nt = 0; nt < 8; nt++)
#pragma unroll
            for (int c = 0; c < 2; c++) {
                const int i = nt * 2 + c;
                const int d = nt * 8 + 2 * tig + c;
                vlo[i] = oacc[nt][c]     + rg[(size_t)d * HW + r0 + gid];
                vhi[i] = oacc[nt][2 + c] + rg[(size_t)d * HW + r0 + gid + 8];
                slo2 += vlo[i]; shi2 += vhi[i];
            }
        slo2 += __shfl_xor_sync(0xffffffffu, slo2, 1);
        slo2 += __shfl_xor_sync(0xffffffffu, slo2, 2);
        shi2 += __shfl_xor_sync(0xffffffffu, shi2, 1);
        shi2 += __shfl_xor_sync(0xffffffffu, shi2, 2);
        const float mlo2 = slo2 * (1.f / 64.f), mhi2 = shi2 * (1.f / 64.f);
        float qlo = 0.f, qhi = 0.f;
#pragma unroll
        for (int i = 0; i < 16; i++) {
            float t1 = vlo[i] - mlo2; qlo += t1 * t1;
            float t2 = vhi[i] - mhi2; qhi += t2 * t2;
        }
        qlo += __shfl_xor_sync(0xffffffffu, qlo, 1);
        qlo += __shfl_xor_sync(0xffffffffu, qlo, 2);
        qhi += __shfl_xor_sync(0xffffffffu, qhi, 1);
        qhi += __shfl_xor_sync(0xffffffffu, qhi, 2);
        const float ilo = 1.f / (sqrtf(qlo * (1.f / 64.f)) + EPSF);
        const float ihi = 1.f / (sqrtf(qhi * (1.f / 64.f)) + EPSF);
#pragma unroll
        for (int nt = 0; nt < 8; nt++)
#pragma unroll
            for (int c = 0; c < 2; c++) {
                const int i = nt * 2 + c;
                const int d = nt * 8 + 2 * tig + c;
                const float lg = lnsm[d], lb = lnsm[64 + d];
                pacc[i] += (vlo[i] - mlo2) * ilo * lg + lb
                         + (vhi[i] - mhi2) * ihi * lg + lb;
            }
    }

#pragma unroll
    for (int i = 0; i < 16; i++) {
        pacc[i] += __shfl_xor_sync(0xffffffffu, pacc[i], 4);
        pacc[i] += __shfl_xor_sync(0xffffffffu, pacc[i], 8);
        pacc[i] += __shfl_xor_sync(0xffffffffu, pacc[i], 16);
    }
    if (gid == 0) {
#pragma unroll
        for (int nt = 0; nt < 8; nt++)
#pragma unroll
            for (int c = 0; c < 2; c++) {
                const int d = nt * 8 + 2 * tig + c;
                pool[warp * 64 + d] = pacc[nt * 2 + c];
            }
    }
    __syncthreads();
    if (tid < 64) {
        float s = 0.f;
#pragma unroll
        for (int w = 0; w < 8; w++) s += pool[w * 64 + tid];
        out[(size_t)bh * 64 + tid] = s * (1.f / 784.f);
    }
}

// =====================================================================
extern "C" void kernel_launch(void* const* d_in, const int* in_sizes, int n_in,
                              void* d_out, int out_size)
{
    const float* x      = (const float*)d_in[0];
    const float* w_dwq  = (const float*)d_in[1];
    const float* w_pwq  = (const float*)d_in[2];
    const float* w_dwkv = (const float*)d_in[3];
    const float* w_pwkv = (const float*)d_in[4];
    const float* w_ds   = (const float*)d_in[5];
    const float* ln_g   = (const float*)d_in[6];
    const float* ln_b   = (const float*)d_in[7];
    const float* bnq_g  = (const float*)d_in[8];
    const float* bnq_b  = (const float*)d_in[9];
    const float* bnq_m  = (const float*)d_in[10];
    const float* bnq_v  = (const float*)d_in[11];
    const float* bnkv_g = (const float*)d_in[12];
    const float* bnkv_b = (const float*)d_in[13];
    const float* bnkv_m = (const float*)d_in[14];
    const float* bnkv_v = (const float*)d_in[15];
    const float* bnds_g = (const float*)d_in[16];
    const float* bnds_b = (const float*)d_in[17];
    const float* bnds_m = (const float*)d_in[18];
    const float* bnds_v = (const float*)d_in[19];
    float* out = (float*)d_out;

    float *p_dwq, *p_dwkv, *p_q, *p_kv, *p_res, *p_wq, *p_wkv, *p_wds;
    cudaGetSymbolAddress((void**)&p_dwq,  g_dwq);
    cudaGetSymbolAddress((void**)&p_dwkv, g_dwkv);
    cudaGetSymbolAddress((void**)&p_q,    g_q);
    cudaGetSymbolAddress((void**)&p_kv,   g_kv);
    cudaGetSymbolAddress((void**)&p_res,  g_res);
    cudaGetSymbolAddress((void**)&p_wq,   g_wq);
    cudaGetSymbolAddress((void**)&p_wkv,  g_wkv);
    cudaGetSymbolAddress((void**)&p_wds,  g_wds);

    const int attn_smem = (2 * 200 * 68 + 512 + 128) * (int)sizeof(float); // 111360
    const int gemm_smem = GEMM_SMEM_FLOATS * (int)sizeof(float);           // 53248

    static cudaStream_t s_side = nullptr;
    static cudaEvent_t ev_fork = nullptr, ev_join = nullptr;
    if (s_side == nullptr) {
        // First call is the uncaptured correctness run: safe to create here.
        cudaStreamCreateWithFlags(&s_side, cudaStreamNonBlocking);
        cudaEventCreateWithFlags(&ev_fork, cudaEventDisableTiming);
        cudaEventCreateWithFlags(&ev_join, cudaEventDisableTiming);
        cudaFuncSetAttribute(attn_tc,
                             cudaFuncAttributeMaxDynamicSharedMemorySize, attn_smem);
        cudaFuncSetAttribute(gemm_tc,
                             cudaFuncAttributeMaxDynamicSharedMemorySize, gemm_smem);
    }

    // ---- fork: side stream runs prep + residual GEMM (depend only on x/weights)
    cudaEventRecord(ev_fork, 0);
    cudaStreamWaitEvent(s_side, ev_fork, 0);

    const int prep_total = PREP_Q_SZ + PREP_KV_SZ + PREP_DS_SZ;
    prep_all<<<(prep_total + 255) / 256, 256, 0, s_side>>>(w_pwq, w_pwkv, w_ds);
    gemm_tc<<<dim3(13, 1, NB), 256, gemm_smem, s_side>>>(p_wds, x, p_res, 128, DH, HW, 0,
                                                         bnds_g, bnds_b, bnds_m, bnds_v);
    cudaEventRecord(ev_join, s_side);

    // ---- main stream: dwconv -> q gemm -> kv gemm
    dwconv_fused<<<NB * NC, 256>>>(x, w_dwq, w_dwkv,
                                   bnq_g, bnq_b, bnq_m, bnq_v,
                                   bnkv_g, bnkv_b, bnkv_m, bnkv_v);

    // q/kv gemms read g_wq/g_wkv written by prep on the side stream; prep
    // finishes well before dwconv (30us vs ~90us+), but correctness must not
    // rely on timing: join the side stream BEFORE the dependent gemms.
    cudaStreamWaitEvent(0, ev_join, 0);

    gemm_tc<<<dim3(13, 4, NB), 256, gemm_smem>>>(p_wq, p_dwq, p_q, 512, INNER, HW, 1,
                                                 nullptr, nullptr, nullptr, nullptr);
    gemm_tc<<<dim3(4, 8, NB), 256, gemm_smem>>>(p_wkv, p_dwkv, p_kv, 1024, 2 * INNER, S2, 1,
                                                nullptr, nullptr, nullptr, nullptr);

    // ---- attention (needs q, kv, res)
    attn_tc<<<NB * NHEADS, 256, attn_smem>>>(ln_g, ln_b, out);
}

// round 13
// speedup vs baseline: 1.1877x; 1.0777x over previous
#include <cuda_runtime.h>
#include <math.h>
#include <stdint.h>

#define NB      64
#define NC      640      // K of all GEMMs
#define HW      784      // 28*28
#define S2      196      // 14*14
#define NHEADS  8
#define DH      64
#define INNER   512      // NHEADS*DH
#define EPSF    1e-5f
#define ATTN_SCALE 0.125f

// ---------------- scratch (device globals; no allocation) ----------------
__device__ float g_dwq [NB * NC * HW];       // dwconv(s1)+BN (tf32-rounded)
__device__ float g_dwkv[NB * NC * S2];       // dwconv(s2)+BN (tf32-rounded)
__device__ float g_q   [NB * INNER * HW];    // q  [b][h*64+d][pos], tf32
__device__ float g_kv  [NB * 2 * INNER * S2];// tf32
__device__ float g_res [NB * DH * HW];       // residual [b][d][pos], fp32
__device__ float g_wq  [NC * 512];           // w_pwq^T  [k][m], tf32
__device__ float g_wkv [NC * 1024];          // w_pwkv^T [k][m], tf32
__device__ float g_wds [NC * 128];           // w_ds^T   [k][m], tf32, zero-padded to 128

// ---------------- helpers ----------------
__device__ __forceinline__ float to_tf32(float v) {
    uint32_t r;
    asm("cvt.rna.tf32.f32 %0, %1;" : "=r"(r) : "f"(v));
    return __uint_as_float(r);
}

__device__ __forceinline__ void cp16(uint32_t dst, const void* src, int src_bytes) {
    asm volatile("cp.async.cg.shared.global [%0], [%1], 16, %2;\n"
                 :: "r"(dst), "l"(src), "r"(src_bytes));
}

__device__ __forceinline__ void mma_tf32(float* c, const uint32_t* a, const uint32_t* b) {
    asm volatile(
        "mma.sync.aligned.m16n8k8.row.col.f32.tf32.tf32.f32 "
        "{%0,%1,%2,%3}, {%4,%5,%6,%7}, {%8,%9}, {%0,%1,%2,%3};\n"
        : "+f"(c[0]), "+f"(c[1]), "+f"(c[2]), "+f"(c[3])
        : "r"(a[0]), "r"(a[1]), "r"(a[2]), "r"(a[3]), "r"(b[0]), "r"(b[1]));
}

// =====================================================================
// Single prep kernel: transpose + tf32-round all three weight matrices.
// =====================================================================
#define PREP_Q_SZ   (NC * 512)
#define PREP_KV_SZ  (NC * 1024)
#define PREP_DS_SZ  (NC * 128)
__global__ void __launch_bounds__(256)
prep_all(const float* __restrict__ wq, const float* __restrict__ wkv,
         const float* __restrict__ wds)
{
    int idx = blockIdx.x * 256 + threadIdx.x;
    if (idx < PREP_Q_SZ) {
        int k = idx / 512, m = idx - k * 512;
        g_wq[idx] = to_tf32(wq[(size_t)m * NC + k]);
    } else if (idx < PREP_Q_SZ + PREP_KV_SZ) {
        int i = idx - PREP_Q_SZ;
        int k = i / 1024, m = i - k * 1024;
        g_wkv[i] = to_tf32(wkv[(size_t)m * NC + k]);
    } else if (idx < PREP_Q_SZ + PREP_KV_SZ + PREP_DS_SZ) {
        int i = idx - PREP_Q_SZ - PREP_KV_SZ;
        int k = i / 128, m = i - k * 128;
        g_wds[i] = (m < 64) ? to_tf32(wds[(size_t)m * NC + k]) : 0.f;
    }
}

// =====================================================================
// Fused depthwise conv (stride1 + stride2) + BN, per (b,c) block.
// =====================================================================
__global__ void __launch_bounds__(256)
dwconv_fused(const float* __restrict__ x,
             const float* __restrict__ wq, const float* __restrict__ wkv,
             const float* __restrict__ qg, const float* __restrict__ qb,
             const float* __restrict__ qm, const float* __restrict__ qvv,
             const float* __restrict__ kg, const float* __restrict__ kb,
             const float* __restrict__ km, const float* __restrict__ kvv)
{
    const int bc = blockIdx.x;
    const int c  = bc % NC;
    __shared__ float xs[30 * 30];
    const int tid = threadIdx.x;
    const int cx = tid & 31, ry = tid >> 5;

    for (int i = tid; i < 900; i += 256) xs[i] = 0.f;
    __syncthreads();
    const float* xp = x + (size_t)bc * HW;
    if (cx < 28) {
        for (int r = ry; r < 28; r += 8)
            xs[(r + 1) * 30 + cx + 1] = xp[r * 28 + cx];
    }
    __syncthreads();

    float wq9[9], wk9[9];
#pragma unroll
    for (int i = 0; i < 9; i++) { wq9[i] = wq[c * 9 + i]; wk9[i] = wkv[c * 9 + i]; }

    const float sq  = qg[c] * rsqrtf(qvv[c] + EPSF);
    const float bq  = qb[c] - qm[c] * sq;
    const float skv = kg[c] * rsqrtf(kvv[c] + EPSF);
    const float bkv = kb[c] - km[c] * skv;

    if (cx < 28) {
        float* oq = g_dwq + (size_t)bc * HW;
        for (int r = ry; r < 28; r += 8) {
            const float* s = &xs[r * 30 + cx];
            float acc = s[0]*wq9[0] + s[1]*wq9[1] + s[2]*wq9[2]
                      + s[30]*wq9[3] + s[31]*wq9[4] + s[32]*wq9[5]
                      + s[60]*wq9[6] + s[61]*wq9[7] + s[62]*wq9[8];
            oq[r * 28 + cx] = to_tf32(acc * sq + bq);
        }
    }
    if (cx < 14) {
        float* okv = g_dwkv + (size_t)bc * S2;
        for (int r = ry; r < 14; r += 8) {
            const float* s = &xs[(r * 2) * 30 + cx * 2];
            float acc = s[0]*wk9[0] + s[1]*wk9[1] + s[2]*wk9[2]
                      + s[30]*wk9[3] + s[31]*wk9[4] + s[32]*wk9[5]
                      + s[60]*wk9[6] + s[61]*wk9[7] + s[62]*wk9[8];
            okv[r * 14 + cx] = to_tf32(acc * skv + bkv);
        }
    }
}

// =====================================================================
// tf32 tensor-core GEMM (R8 config: 128x64x32, 4 blocks/SM)
// =====================================================================
#define GEMM_SMEM_FLOATS (2 * (32 * 136 + 32 * 72))
__global__ void __launch_bounds__(256)
gemm_tc(const float* __restrict__ wT, const float* __restrict__ act,
        float* __restrict__ Cc, int Mpad, int M, int N, int round_out,
        const float* __restrict__ bg, const float* __restrict__ bb,
        const float* __restrict__ bm, const float* __restrict__ bv)
{
    extern __shared__ float sm[];
    const int tid  = threadIdx.x;
    const int lane = tid & 31, warp = tid >> 5;
    const int wm = (warp >> 1) * 32;
    const int wn = (warp & 1) * 32;
    const int n0 = blockIdx.x * 64;
    const int m0 = blockIdx.y * 128;
    const float* Ab = act + (size_t)blockIdx.z * NC * N;
    float*       Cb = Cc  + (size_t)blockIdx.z * (size_t)M * N;

    float acc[2][4][4];
#pragma unroll
    for (int i = 0; i < 2; i++)
#pragma unroll
        for (int j = 0; j < 4; j++)
#pragma unroll
            for (int l = 0; l < 4; l++) acc[i][j][l] = 0.f;

    const int a_k = tid >> 5, a_m4 = (tid & 31) * 4;
    const int b_k = tid >> 4, b_n4 = (tid & 15) * 4;

    auto load_tile = [&](int k0, int st) {
        float* As = sm + st * (32 * 136 + 32 * 72);
        float* Bs = As + 32 * 136;
#pragma unroll
        for (int i = 0; i < 4; i++) {
            int k = a_k + i * 8;
            uint32_t dst = (uint32_t)__cvta_generic_to_shared(&As[k * 136 + a_m4]);
            cp16(dst, wT + (size_t)(k0 + k) * Mpad + m0 + a_m4, 16);
        }
#pragma unroll
        for (int i = 0; i < 2; i++) {
            int k = b_k + i * 16;
            int col = n0 + b_n4;
            uint32_t dst = (uint32_t)__cvta_generic_to_shared(&Bs[k * 72 + b_n4]);
            cp16(dst, Ab + (size_t)(k0 + k) * N + col, (col < N) ? 16 : 0);
        }
        asm volatile("cp.async.commit_group;\n");
    };

    load_tile(0, 0);
    for (int t = 0; t < 20; t++) {
        const int st = t & 1;
        if (t < 19) {
            load_tile((t + 1) * 32, st ^ 1);
            asm volatile("cp.async.wait_group 1;\n");
        } else {
            asm volatile("cp.async.wait_group 0;\n");
        }
        __syncthreads();
        const float* As = sm + st * (32 * 136 + 32 * 72);
        const float* Bs = As + 32 * 136;
#pragma unroll
        for (int kk = 0; kk < 32; kk += 8) {
            uint32_t af[2][4], bf[4][2];
            const int kq   = kk + (lane & 3);
            const int mrow = wm + (lane >> 2);
            const int ncol = wn + (lane >> 2);
#pragma unroll
            for (int mt = 0; mt < 2; mt++) {
                af[mt][0] = __float_as_uint(As[kq * 136 + mrow + mt * 16]);
                af[mt][1] = __float_as_uint(As[kq * 136 + mrow + mt * 16 + 8]);
                af[mt][2] = __float_as_uint(As[(kq + 4) * 136 + mrow + mt * 16]);
                af[mt][3] = __float_as_uint(As[(kq + 4) * 136 + mrow + mt * 16 + 8]);
            }
#pragma unroll
            for (int nt = 0; nt < 4; nt++) {
                bf[nt][0] = __float_as_uint(Bs[kq * 72 + ncol + nt * 8]);
                bf[nt][1] = __float_as_uint(Bs[(kq + 4) * 72 + ncol + nt * 8]);
            }
#pragma unroll
            for (int mt = 0; mt < 2; mt++)
#pragma unroll
                for (int nt = 0; nt < 4; nt++)
                    mma_tf32(acc[mt][nt], af[mt], bf[nt]);
        }
        __syncthreads();
    }

    const bool has_bn = (bg != nullptr);
#pragma unroll
    for (int mt = 0; mt < 2; mt++) {
#pragma unroll
        for (int half = 0; half < 2; half++) {
            const int m = m0 + wm + mt * 16 + (lane >> 2) + half * 8;
            if (m >= M) continue;
            float sc = 1.f, bi = 0.f;
            if (has_bn) { sc = bg[m] * rsqrtf(bv[m] + EPSF); bi = bb[m] - bm[m] * sc; }
#pragma unroll
            for (int nt = 0; nt < 4; nt++) {
                const int n = n0 + wn + nt * 8 + 2 * (lane & 3);
                if (n < N) {
                    float2 v;
                    v.x = acc[mt][nt][half * 2 + 0] * sc + bi;
                    v.y = acc[mt][nt][half * 2 + 1] * sc + bi;
                    if (round_out) { v.x = to_tf32(v.x); v.y = to_tf32(v.y); }
                    *(float2*)&Cb[(size_t)m * N + n] = v;
                }
            }
        }
    }
}

// =====================================================================
// Tensor-core attention, flash-style two-half key split (13+12 tiles)
// to cut live registers -> 2 blocks/SM. Online max/sum merge.
// =====================================================================
__global__ void __launch_bounds__(256, 2)
attn_tc(const float* __restrict__ lnw, const float* __restrict__ lnbp,
        float* __restrict__ out)
{
    const int bh = blockIdx.x;
    const int b  = bh >> 3;
    const int h  = bh & 7;

    extern __shared__ __align__(16) float sm[];
    float* ksm  = sm;                    // [200][68]
    float* vsm  = ksm + 200 * 68;        // [200][68]
    float* pool = vsm + 200 * 68;        // [8][64]
    float* lnsm = pool + 512;            // gamma[64], beta[64]

    const int tid  = threadIdx.x;
    const int lane = tid & 31, warp = tid >> 5;
    const int gid  = lane >> 2, tig = lane & 3;

    const float* kg = g_kv + ((size_t)b * 1024 + h * 64) * S2;
    const float* vg = g_kv + ((size_t)b * 1024 + 512 + h * 64) * S2;
    for (int idx = tid; idx < 200 * 64; idx += 256) {
        int j = idx % 200, d = idx / 200;
        ksm[j * 68 + d] = (j < S2) ? kg[(size_t)d * S2 + j] : 0.f;
        vsm[j * 68 + d] = (j < S2) ? vg[(size_t)d * S2 + j] : 0.f;
    }
    if (tid < 128) lnsm[tid] = (tid < 64) ? lnw[h * 64 + tid] : lnbp[h * 64 + tid - 64];
    __syncthreads();

    float pacc[16];
#pragma unroll
    for (int i = 0; i < 16; i++) pacc[i] = 0.f;

    const float* qg = g_q + ((size_t)b * INNER + h * 64) * HW;
    const float* rg = g_res + (size_t)b * DH * HW;

    const int srcLow  = (lane & ~3) | (tig >> 1);
    const int srcHigh = srcLow + 2;
    const bool odd = (tig & 1) != 0;

    for (int t = warp; t < 49; t += 8) {
        const int r0 = t * 16;

        float oacc[8][4];
#pragma unroll
        for (int nt = 0; nt < 8; nt++) {
            oacc[nt][0] = oacc[nt][1] = oacc[nt][2] = oacc[nt][3] = 0.f;
        }
        float mlo, mhi, llo, lhi;

        // ================= half 0: key tiles 0..12 (keys 0..103) =========
        {
            float sacc[13][4];
#pragma unroll
            for (int nt = 0; nt < 13; nt++) {
                sacc[nt][0] = sacc[nt][1] = sacc[nt][2] = sacc[nt][3] = 0.f;
            }
#pragma unroll
            for (int kk = 0; kk < 8; kk++) {
                const int d0 = kk * 8 + tig;
                uint32_t a[4];
                a[0] = __float_as_uint(qg[(size_t)d0 * HW + r0 + gid]);
                a[1] = __float_as_uint(qg[(size_t)d0 * HW + r0 + gid + 8]);
                a[2] = __float_as_uint(qg[(size_t)(d0 + 4) * HW + r0 + gid]);
                a[3] = __float_as_uint(qg[(size_t)(d0 + 4) * HW + r0 + gid + 8]);
#pragma unroll
                for (int nt = 0; nt < 13; nt++) {
                    uint32_t bfr[2];
                    bfr[0] = __float_as_uint(ksm[(nt * 8 + gid) * 68 + d0]);
                    bfr[1] = __float_as_uint(ksm[(nt * 8 + gid) * 68 + d0 + 4]);
                    mma_tf32(sacc[nt], a, bfr);
                }
            }
            mlo = -1e30f; mhi = -1e30f;
#pragma unroll
            for (int nt = 0; nt < 13; nt++) {
                mlo = fmaxf(mlo, fmaxf(sacc[nt][0], sacc[nt][1]));
                mhi = fmaxf(mhi, fmaxf(sacc[nt][2], sacc[nt][3]));
            }
            mlo = fmaxf(mlo, __shfl_xor_sync(0xffffffffu, mlo, 1));
            mlo = fmaxf(mlo, __shfl_xor_sync(0xffffffffu, mlo, 2));
            mhi = fmaxf(mhi, __shfl_xor_sync(0xffffffffu, mhi, 1));
            mhi = fmaxf(mhi, __shfl_xor_sync(0xffffffffu, mhi, 2));
            const float mls = mlo * ATTN_SCALE, mhs = mhi * ATTN_SCALE;
            llo = 0.f; lhi = 0.f;
#pragma unroll
            for (int nt = 0; nt < 13; nt++) {
                float e0 = __expf(fmaf(sacc[nt][0], ATTN_SCALE, -mls));
                float e1 = __expf(fmaf(sacc[nt][1], ATTN_SCALE, -mls));
                float e2 = __expf(fmaf(sacc[nt][2], ATTN_SCALE, -mhs));
                float e3 = __expf(fmaf(sacc[nt][3], ATTN_SCALE, -mhs));
                sacc[nt][0] = e0; sacc[nt][1] = e1; sacc[nt][2] = e2; sacc[nt][3] = e3;
                llo += e0 + e1; lhi += e2 + e3;
            }
            llo += __shfl_xor_sync(0xffffffffu, llo, 1);
            llo += __shfl_xor_sync(0xffffffffu, llo, 2);
            lhi += __shfl_xor_sync(0xffffffffu, lhi, 1);
            lhi += __shfl_xor_sync(0xffffffffu, lhi, 2);

#pragma unroll
            for (int kk = 0; kk < 13; kk++) {
                float u0 = __shfl_sync(0xffffffffu, sacc[kk][0], srcLow);
                float u1 = __shfl_sync(0xffffffffu, sacc[kk][1], srcLow);
                float w0 = __shfl_sync(0xffffffffu, sacc[kk][2], srcLow);
                float w1 = __shfl_sync(0xffffffffu, sacc[kk][3], srcLow);
                float v0 = __shfl_sync(0xffffffffu, sacc[kk][0], srcHigh);
                float v1 = __shfl_sync(0xffffffffu, sacc[kk][1], srcHigh);
                float z0 = __shfl_sync(0xffffffffu, sacc[kk][2], srcHigh);
                float z1 = __shfl_sync(0xffffffffu, sacc[kk][3], srcHigh);
                uint32_t a[4];
                a[0] = __float_as_uint(odd ? u1 : u0);
                a[1] = __float_as_uint(odd ? w1 : w0);
                a[2] = __float_as_uint(odd ? v1 : v0);
                a[3] = __float_as_uint(odd ? z1 : z0);
                const int j0 = kk * 8 + tig;
#pragma unroll
                for (int nt = 0; nt < 8; nt++) {
                    uint32_t bfr[2];
                    bfr[0] = __float_as_uint(vsm[j0 * 68 + nt * 8 + gid]);
                    bfr[1] = __float_as_uint(vsm[(j0 + 4) * 68 + nt * 8 + gid]);
                    mma_tf32(oacc[nt], a, bfr);
                }
            }
        }

        // ================= half 1: key tiles 13..24 (keys 104..199) ======
        {
            float sacc[12][4];
#pragma unroll
            for (int nt = 0; nt < 12; nt++) {
                sacc[nt][0] = sacc[nt][1] = sacc[nt][2] = sacc[nt][3] = 0.f;
            }
#pragma unroll
            for (int kk = 0; kk < 8; kk++) {
                const int d0 = kk * 8 + tig;
                uint32_t a[4];
                a[0] = __float_as_uint(qg[(size_t)d0 * HW + r0 + gid]);
                a[1] = __float_as_uint(qg[(size_t)d0 * HW + r0 + gid + 8]);
                a[2] = __float_as_uint(qg[(size_t)(d0 + 4) * HW + r0 + gid]);
                a[3] = __float_as_uint(qg[(size_t)(d0 + 4) * HW + r0 + gid + 8]);
#pragma unroll
                for (int nt = 0; nt < 12; nt++) {
                    uint32_t bfr[2];
                    bfr[0] = __float_as_uint(ksm[((13 + nt) * 8 + gid) * 68 + d0]);
                    bfr[1] = __float_as_uint(ksm[((13 + nt) * 8 + gid) * 68 + d0 + 4]);
                    mma_tf32(sacc[nt], a, bfr);
                }
            }
            // mask padded cols (global tile 24 = local 11: cols 192+2*tig(+1))
            if (tig >= 2) {
                sacc[11][0] = sacc[11][1] = sacc[11][2] = sacc[11][3] = -1e30f;
            }

            float m1lo = -1e30f, m1hi = -1e30f;
#pragma unroll
            for (int nt = 0; nt < 12; nt++) {
                m1lo = fmaxf(m1lo, fmaxf(sacc[nt][0], sacc[nt][1]));
                m1hi = fmaxf(m1hi, fmaxf(sacc[nt][2], sacc[nt][3]));
            }
            m1lo = fmaxf(m1lo, __shfl_xor_sync(0xffffffffu, m1lo, 1));
            m1lo = fmaxf(m1lo, __shfl_xor_sync(0xffffffffu, m1lo, 2));
            m1hi = fmaxf(m1hi, __shfl_xor_sync(0xffffffffu, m1hi, 1));
            m1hi = fmaxf(m1hi, __shfl_xor_sync(0xffffffffu, m1hi, 2));
            const float nmlo = fmaxf(mlo, m1lo), nmhi = fmaxf(mhi, m1hi);
            const float clo = __expf((mlo - nmlo) * ATTN_SCALE);
            const float chi = __expf((mhi - nmhi) * ATTN_SCALE);
            const float mls = nmlo * ATTN_SCALE, mhs = nmhi * ATTN_SCALE;
            float s1lo = 0.f, s1hi = 0.f;
#pragma unroll
            for (int nt = 0; nt < 12; nt++) {
                float e0 = __expf(fmaf(sacc[nt][0], ATTN_SCALE, -mls));
                float e1 = __expf(fmaf(sacc[nt][1], ATTN_SCALE, -mls));
                float e2 = __expf(fmaf(sacc[nt][2], ATTN_SCALE, -mhs));
                float e3 = __expf(fmaf(sacc[nt][3], ATTN_SCALE, -mhs));
                sacc[nt][0] = e0; sacc[nt][1] = e1; sacc[nt][2] = e2; sacc[nt][3] = e3;
                s1lo += e0 + e1; s1hi += e2 + e3;
            }
            s1lo += __shfl_xor_sync(0xffffffffu, s1lo, 1);
            s1lo += __shfl_xor_sync(0xffffffffu, s1lo, 2);
            s1hi += __shfl_xor_sync(0xffffffffu, s1hi, 1);
            s1hi += __shfl_xor_sync(0xffffffffu, s1hi, 2);
            llo = llo * clo + s1lo;
            lhi = lhi * chi + s1hi;
#pragma unroll
            for (int nt = 0; nt < 8; nt++) {
                oacc[nt][0] *= clo; oacc[nt][1] *= clo;
                oacc[nt][2] *= chi; oacc[nt][3] *= chi;
            }

#pragma unroll
            for (int kk = 0; kk < 12; kk++) {
                float u0 = __shfl_sync(0xffffffffu, sacc[kk][0], srcLow);
                float u1 = __shfl_sync(0xffffffffu, sacc[kk][1], srcLow);
                float w0 = __shfl_sync(0xffffffffu, sacc[kk][2], srcLow);
                float w1 = __shfl_sync(0xffffffffu, sacc[kk][3], srcLow);
                float v0 = __shfl_sync(0xffffffffu, sacc[kk][0], srcHigh);
                float v1 = __shfl_sync(0xffffffffu, sacc[kk][1], srcHigh);
                float z0 = __shfl_sync(0xffffffffu, sacc[kk][2], srcHigh);
                float z1 = __shfl_sync(0xffffffffu, sacc[kk][3], srcHigh);
                uint32_t a[4];
                a[0] = __float_as_uint(odd ? u1 : u0);
                a[1] = __float_as_uint(odd ? w1 : w0);
                a[2] = __float_as_uint(odd ? v1 : v0);
                a[3] = __float_as_uint(odd ? z1 : z0);
                const int j0 = (13 + kk) * 8 + tig;
#pragma unroll
                for (int nt = 0; nt < 8; nt++) {
                    uint32_t bfr[2];
                    bfr[0] = __float_as_uint(vsm[j0 * 68 + nt * 8 + gid]);
                    bfr[1] = __float_as_uint(vsm[(j0 + 4) * 68 + nt * 8 + gid]);
                    mma_tf32(oacc[nt], a, bfr);
                }
            }
        }

        // ---- epilogue: normalize + residual + LayerNorm + pool ----
        const float rlo2 = 1.f / llo, rhi2 = 1.f / lhi;
        float vlo[16], vhi[16];
        float slo2 = 0.f, shi2 = 0.f;
#pragma unroll
        for (int nt = 0; nt < 8; nt++)
#pragma unroll
            for (int c = 0; c < 2; c++) {
                const int i = nt * 2 + c;
                const int d = nt * 8 + 2 * tig + c;
                vlo[i] = oacc[nt][c]     * rlo2 + rg[(size_t)d * HW + r0 + gid];
                vhi[i] = oacc[nt][2 + c] * rhi2 + rg[(size_t)d * HW + r0 + gid + 8];
                slo2 += vlo[i]; shi2 += vhi[i];
            }
        slo2 += __shfl_xor_sync(0xffffffffu, slo2, 1);
        slo2 += __shfl_xor_sync(0xffffffffu, slo2, 2);
        shi2 += __shfl_xor_sync(0xffffffffu, shi2, 1);
        shi2 += __shfl_xor_sync(0xffffffffu, shi2, 2);
        const float mlo2 = slo2 * (1.f / 64.f), mhi2 = shi2 * (1.f / 64.f);
        float qlo = 0.f, qhi = 0.f;
#pragma unroll
        for (int i = 0; i < 16; i++) {
            float t1 = vlo[i] - mlo2; qlo += t1 * t1;
            float t2 = vhi[i] - mhi2; qhi += t2 * t2;
        }
        qlo += __shfl_xor_sync(0xffffffffu, qlo, 1);
        qlo += __shfl_xor_sync(0xffffffffu, qlo, 2);
        qhi += __shfl_xor_sync(0xffffffffu, qhi, 1);
        qhi += __shfl_xor_sync(0xffffffffu, qhi, 2);
        const float ilo = 1.f / (sqrtf(qlo * (1.f / 64.f)) + EPSF);
        const float ihi = 1.f / (sqrtf(qhi * (1.f / 64.f)) + EPSF);
#pragma unroll
        for (int nt = 0; nt < 8; nt++)
#pragma unroll
            for (int c = 0; c < 2; c++) {
                const int i = nt * 2 + c;
                const int d = nt * 8 + 2 * tig + c;
                const float lg = lnsm[d], lb = lnsm[64 + d];
                pacc[i] += (vlo[i] - mlo2) * ilo * lg + lb
                         + (vhi[i] - mhi2) * ihi * lg + lb;
            }
    }

#pragma unroll
    for (int i = 0; i < 16; i++) {
        pacc[i] += __shfl_xor_sync(0xffffffffu, pacc[i], 4);
        pacc[i] += __shfl_xor_sync(0xffffffffu, pacc[i], 8);
        pacc[i] += __shfl_xor_sync(0xffffffffu, pacc[i], 16);
    }
    if (gid == 0) {
#pragma unroll
        for (int nt = 0; nt < 8; nt++)
#pragma unroll
            for (int c = 0; c < 2; c++) {
                const int d = nt * 8 + 2 * tig + c;
                pool[warp * 64 + d] = pacc[nt * 2 + c];
            }
    }
    __syncthreads();
    if (tid < 64) {
        float s = 0.f;
#pragma unroll
        for (int w = 0; w < 8; w++) s += pool[w * 64 + tid];
        out[(size_t)bh * 64 + tid] = s * (1.f / 784.f);
    }
}

// =====================================================================
extern "C" void kernel_launch(void* const* d_in, const int* in_sizes, int n_in,
                              void* d_out, int out_size)
{
    const float* x      = (const float*)d_in[0];
    const float* w_dwq  = (const float*)d_in[1];
    const float* w_pwq  = (const float*)d_in[2];
    const float* w_dwkv = (const float*)d_in[3];
    const float* w_pwkv = (const float*)d_in[4];
    const float* w_ds   = (const float*)d_in[5];
    const float* ln_g   = (const float*)d_in[6];
    const float* ln_b   = (const float*)d_in[7];
    const float* bnq_g  = (const float*)d_in[8];
    const float* bnq_b  = (const float*)d_in[9];
    const float* bnq_m  = (const float*)d_in[10];
    const float* bnq_v  = (const float*)d_in[11];
    const float* bnkv_g = (const float*)d_in[12];
    const float* bnkv_b = (const float*)d_in[13];
    const float* bnkv_m = (const float*)d_in[14];
    const float* bnkv_v = (const float*)d_in[15];
    const float* bnds_g = (const float*)d_in[16];
    const float* bnds_b = (const float*)d_in[17];
    const float* bnds_m = (const float*)d_in[18];
    const float* bnds_v = (const float*)d_in[19];
    float* out = (float*)d_out;

    float *p_dwq, *p_dwkv, *p_q, *p_kv, *p_res, *p_wq, *p_wkv, *p_wds;
    cudaGetSymbolAddress((void**)&p_dwq,  g_dwq);
    cudaGetSymbolAddress((void**)&p_dwkv, g_dwkv);
    cudaGetSymbolAddress((void**)&p_q,    g_q);
    cudaGetSymbolAddress((void**)&p_kv,   g_kv);
    cudaGetSymbolAddress((void**)&p_res,  g_res);
    cudaGetSymbolAddress((void**)&p_wq,   g_wq);
    cudaGetSymbolAddress((void**)&p_wkv,  g_wkv);
    cudaGetSymbolAddress((void**)&p_wds,  g_wds);

    const int attn_smem = (2 * 200 * 68 + 512 + 128) * (int)sizeof(float); // 111360
    const int gemm_smem = GEMM_SMEM_FLOATS * (int)sizeof(float);           // 53248

    static cudaStream_t s_side = nullptr;
    static cudaEvent_t ev_fork = nullptr, ev_join = nullptr;
    if (s_side == nullptr) {
        cudaStreamCreateWithFlags(&s_side, cudaStreamNonBlocking);
        cudaEventCreateWithFlags(&ev_fork, cudaEventDisableTiming);
        cudaEventCreateWithFlags(&ev_join, cudaEventDisableTiming);
        cudaFuncSetAttribute(attn_tc,
                             cudaFuncAttributeMaxDynamicSharedMemorySize, attn_smem);
        cudaFuncSetAttribute(gemm_tc,
                             cudaFuncAttributeMaxDynamicSharedMemorySize, gemm_smem);
    }

    // ---- fork: side stream runs prep + residual GEMM
    cudaEventRecord(ev_fork, 0);
    cudaStreamWaitEvent(s_side, ev_fork, 0);

    const int prep_total = PREP_Q_SZ + PREP_KV_SZ + PREP_DS_SZ;
    prep_all<<<(prep_total + 255) / 256, 256, 0, s_side>>>(w_pwq, w_pwkv, w_ds);
    gemm_tc<<<dim3(13, 1, NB), 256, gemm_smem, s_side>>>(p_wds, x, p_res, 128, DH, HW, 0,
                                                         bnds_g, bnds_b, bnds_m, bnds_v);
    cudaEventRecord(ev_join, s_side);

    // ---- main stream: dwconv -> q gemm -> kv gemm
    dwconv_fused<<<NB * NC, 256>>>(x, w_dwq, w_dwkv,
                                   bnq_g, bnq_b, bnq_m, bnq_v,
                                   bnkv_g, bnkv_b, bnkv_m, bnkv_v);

    cudaStreamWaitEvent(0, ev_join, 0);

    gemm_tc<<<dim3(13, 4, NB), 256, gemm_smem>>>(p_wq, p_dwq, p_q, 512, INNER, HW, 1,
                                                 nullptr, nullptr, nullptr, nullptr);
    gemm_tc<<<dim3(4, 8, NB), 256, gemm_smem>>>(p_wkv, p_dwkv, p_kv, 1024, 2 * INNER, S2, 1,
                                                nullptr, nullptr, nullptr, nullptr);

    // ---- attention (needs q, kv, res)
    attn_tc<<<NB * NHEADS, 256, attn_smem>>>(ln_g, ln_b, out);
}

// round 14
// speedup vs baseline: 1.2554x; 1.0570x over previous
#include <cuda_runtime.h>
#include <math.h>
#include <stdint.h>

#define NB      64
#define NC      640      // K of all GEMMs
#define HW      784      // 28*28
#define S2      196      // 14*14
#define NHEADS  8
#define DH      64
#define INNER   512      // NHEADS*DH
#define EPSF    1e-5f
#define ATTN_SCALE 0.125f
#define KST     68       // ksm stride (phase A conflict-free: 4*gid+tig)
#define VST     72       // vsm stride (phase B conflict-free: 8*tig+gid)

// ---------------- scratch (device globals; no allocation) ----------------
__device__ float g_dwq [NB * NC * HW];       // dwconv(s1)+BN (tf32-rounded)
__device__ float g_dwkv[NB * NC * S2];       // dwconv(s2)+BN (tf32-rounded)
__device__ float g_q   [NB * INNER * HW];    // q  [b][h*64+d][pos], tf32
__device__ float g_kv  [NB * 2 * INNER * S2];// tf32
__device__ float g_res [NB * DH * HW];       // residual [b][d][pos], fp32
__device__ float g_wq  [NC * 512];           // w_pwq^T  [k][m], tf32
__device__ float g_wkv [NC * 1024];          // w_pwkv^T [k][m], tf32
__device__ float g_wds [NC * 128];           // w_ds^T   [k][m], tf32, zero-padded to 128

// ---------------- helpers ----------------
__device__ __forceinline__ float to_tf32(float v) {
    uint32_t r;
    asm("cvt.rna.tf32.f32 %0, %1;" : "=r"(r) : "f"(v));
    return __uint_as_float(r);
}

__device__ __forceinline__ void cp16(uint32_t dst, const void* src, int src_bytes) {
    asm volatile("cp.async.cg.shared.global [%0], [%1], 16, %2;\n"
                 :: "r"(dst), "l"(src), "r"(src_bytes));
}

__device__ __forceinline__ void mma_tf32(float* c, const uint32_t* a, const uint32_t* b) {
    asm volatile(
        "mma.sync.aligned.m16n8k8.row.col.f32.tf32.tf32.f32 "
        "{%0,%1,%2,%3}, {%4,%5,%6,%7}, {%8,%9}, {%0,%1,%2,%3};\n"
        : "+f"(c[0]), "+f"(c[1]), "+f"(c[2]), "+f"(c[3])
        : "r"(a[0]), "r"(a[1]), "r"(a[2]), "r"(a[3]), "r"(b[0]), "r"(b[1]));
}

// =====================================================================
// Single prep kernel: transpose + tf32-round all three weight matrices.
// =====================================================================
#define PREP_Q_SZ   (NC * 512)
#define PREP_KV_SZ  (NC * 1024)
#define PREP_DS_SZ  (NC * 128)
__global__ void __launch_bounds__(256)
prep_all(const float* __restrict__ wq, const float* __restrict__ wkv,
         const float* __restrict__ wds)
{
    int idx = blockIdx.x * 256 + threadIdx.x;
    if (idx < PREP_Q_SZ) {
        int k = idx / 512, m = idx - k * 512;
        g_wq[idx] = to_tf32(wq[(size_t)m * NC + k]);
    } else if (idx < PREP_Q_SZ + PREP_KV_SZ) {
        int i = idx - PREP_Q_SZ;
        int k = i / 1024, m = i - k * 1024;
        g_wkv[i] = to_tf32(wkv[(size_t)m * NC + k]);
    } else if (idx < PREP_Q_SZ + PREP_KV_SZ + PREP_DS_SZ) {
        int i = idx - PREP_Q_SZ - PREP_KV_SZ;
        int k = i / 128, m = i - k * 128;
        g_wds[i] = (m < 64) ? to_tf32(wds[(size_t)m * NC + k]) : 0.f;
    }
}

// =====================================================================
// Fused depthwise conv (stride1 + stride2) + BN, per (b,c) block.
// Zero only the 116 halo cells; interior written directly.
// =====================================================================
__global__ void __launch_bounds__(256)
dwconv_fused(const float* __restrict__ x,
             const float* __restrict__ wq, const float* __restrict__ wkv,
             const float* __restrict__ qg, const float* __restrict__ qb,
             const float* __restrict__ qm, const float* __restrict__ qvv,
             const float* __restrict__ kg, const float* __restrict__ kb,
             const float* __restrict__ km, const float* __restrict__ kvv)
{
    const int bc = blockIdx.x;
    const int c  = bc % NC;
    __shared__ float xs[30 * 30];
    const int tid = threadIdx.x;
    const int cx = tid & 31, ry = tid >> 5;

    // zero halo (116 cells), single pass (116 < 256)
    if (tid < 116) {
        int idx;
        if (tid < 30)       idx = tid;                       // top row
        else if (tid < 60)  idx = 29 * 30 + (tid - 30);      // bottom row
        else if (tid < 88)  idx = (tid - 60 + 1) * 30;       // left col rows 1..28
        else                idx = (tid - 88 + 1) * 30 + 29;  // right col rows 1..28
        xs[idx] = 0.f;
    }
    const float* xp = x + (size_t)bc * HW;
    if (cx < 28) {
        for (int r = ry; r < 28; r += 8)
            xs[(r + 1) * 30 + cx + 1] = xp[r * 28 + cx];
    }
    __syncthreads();

    float wq9[9], wk9[9];
#pragma unroll
    for (int i = 0; i < 9; i++) { wq9[i] = wq[c * 9 + i]; wk9[i] = wkv[c * 9 + i]; }

    const float sq  = qg[c] * rsqrtf(qvv[c] + EPSF);
    const float bq  = qb[c] - qm[c] * sq;
    const float skv = kg[c] * rsqrtf(kvv[c] + EPSF);
    const float bkv = kb[c] - km[c] * skv;

    if (cx < 28) {
        float* oq = g_dwq + (size_t)bc * HW;
        for (int r = ry; r < 28; r += 8) {
            const float* s = &xs[r * 30 + cx];
            float acc = s[0]*wq9[0] + s[1]*wq9[1] + s[2]*wq9[2]
                      + s[30]*wq9[3] + s[31]*wq9[4] + s[32]*wq9[5]
                      + s[60]*wq9[6] + s[61]*wq9[7] + s[62]*wq9[8];
            oq[r * 28 + cx] = to_tf32(acc * sq + bq);
        }
    }
    if (cx < 14) {
        float* okv = g_dwkv + (size_t)bc * S2;
        for (int r = ry; r < 14; r += 8) {
            const float* s = &xs[(r * 2) * 30 + cx * 2];
            float acc = s[0]*wk9[0] + s[1]*wk9[1] + s[2]*wk9[2]
                      + s[30]*wk9[3] + s[31]*wk9[4] + s[32]*wk9[5]
                      + s[60]*wk9[6] + s[61]*wk9[7] + s[62]*wk9[8];
            okv[r * 14 + cx] = to_tf32(acc * skv + bkv);
        }
    }
}

// =====================================================================
// tf32 tensor-core GEMM (R8 config: 128x64x32, 4 blocks/SM)
// =====================================================================
#define GEMM_SMEM_FLOATS (2 * (32 * 136 + 32 * 72))
__global__ void __launch_bounds__(256)
gemm_tc(const float* __restrict__ wT, const float* __restrict__ act,
        float* __restrict__ Cc, int Mpad, int M, int N, int round_out,
        const float* __restrict__ bg, const float* __restrict__ bb,
        const float* __restrict__ bm, const float* __restrict__ bv)
{
    extern __shared__ float sm[];
    const int tid  = threadIdx.x;
    const int lane = tid & 31, warp = tid >> 5;
    const int wm = (warp >> 1) * 32;
    const int wn = (warp & 1) * 32;
    const int n0 = blockIdx.x * 64;
    const int m0 = blockIdx.y * 128;
    const float* Ab = act + (size_t)blockIdx.z * NC * N;
    float*       Cb = Cc  + (size_t)blockIdx.z * (size_t)M * N;

    float acc[2][4][4];
#pragma unroll
    for (int i = 0; i < 2; i++)
#pragma unroll
        for (int j = 0; j < 4; j++)
#pragma unroll
            for (int l = 0; l < 4; l++) acc[i][j][l] = 0.f;

    const int a_k = tid >> 5, a_m4 = (tid & 31) * 4;
    const int b_k = tid >> 4, b_n4 = (tid & 15) * 4;

    auto load_tile = [&](int k0, int st) {
        float* As = sm + st * (32 * 136 + 32 * 72);
        float* Bs = As + 32 * 136;
#pragma unroll
        for (int i = 0; i < 4; i++) {
            int k = a_k + i * 8;
            uint32_t dst = (uint32_t)__cvta_generic_to_shared(&As[k * 136 + a_m4]);
            cp16(dst, wT + (size_t)(k0 + k) * Mpad + m0 + a_m4, 16);
        }
#pragma unroll
        for (int i = 0; i < 2; i++) {
            int k = b_k + i * 16;
            int col = n0 + b_n4;
            uint32_t dst = (uint32_t)__cvta_generic_to_shared(&Bs[k * 72 + b_n4]);
            cp16(dst, Ab + (size_t)(k0 + k) * N + col, (col < N) ? 16 : 0);
        }
        asm volatile("cp.async.commit_group;\n");
    };

    load_tile(0, 0);
    for (int t = 0; t < 20; t++) {
        const int st = t & 1;
        if (t < 19) {
            load_tile((t + 1) * 32, st ^ 1);
            asm volatile("cp.async.wait_group 1;\n");
        } else {
            asm volatile("cp.async.wait_group 0;\n");
        }
        __syncthreads();
        const float* As = sm + st * (32 * 136 + 32 * 72);
        const float* Bs = As + 32 * 136;
#pragma unroll
        for (int kk = 0; kk < 32; kk += 8) {
            uint32_t af[2][4], bf[4][2];
            const int kq   = kk + (lane & 3);
            const int mrow = wm + (lane >> 2);
            const int ncol = wn + (lane >> 2);
#pragma unroll
            for (int mt = 0; mt < 2; mt++) {
                af[mt][0] = __float_as_uint(As[kq * 136 + mrow + mt * 16]);
                af[mt][1] = __float_as_uint(As[kq * 136 + mrow + mt * 16 + 8]);
                af[mt][2] = __float_as_uint(As[(kq + 4) * 136 + mrow + mt * 16]);
                af[mt][3] = __float_as_uint(As[(kq + 4) * 136 + mrow + mt * 16 + 8]);
            }
#pragma unroll
            for (int nt = 0; nt < 4; nt++) {
                bf[nt][0] = __float_as_uint(Bs[kq * 72 + ncol + nt * 8]);
                bf[nt][1] = __float_as_uint(Bs[(kq + 4) * 72 + ncol + nt * 8]);
            }
#pragma unroll
            for (int mt = 0; mt < 2; mt++)
#pragma unroll
                for (int nt = 0; nt < 4; nt++)
                    mma_tf32(acc[mt][nt], af[mt], bf[nt]);
        }
        __syncthreads();
    }

    const bool has_bn = (bg != nullptr);
#pragma unroll
    for (int mt = 0; mt < 2; mt++) {
#pragma unroll
        for (int half = 0; half < 2; half++) {
            const int m = m0 + wm + mt * 16 + (lane >> 2) + half * 8;
            if (m >= M) continue;
            float sc = 1.f, bi = 0.f;
            if (has_bn) { sc = bg[m] * rsqrtf(bv[m] + EPSF); bi = bb[m] - bm[m] * sc; }
#pragma unroll
            for (int nt = 0; nt < 4; nt++) {
                const int n = n0 + wn + nt * 8 + 2 * (lane & 3);
                if (n < N) {
                    float2 v;
                    v.x = acc[mt][nt][half * 2 + 0] * sc + bi;
                    v.y = acc[mt][nt][half * 2 + 1] * sc + bi;
                    if (round_out) { v.x = to_tf32(v.x); v.y = to_tf32(v.y); }
                    *(float2*)&Cb[(size_t)m * N + n] = v;
                }
            }
        }
    }
}

// =====================================================================
// Tensor-core attention, flash-style two-half key split, 2 blocks/SM.
// ksm stride 68 (phase A conflict-free), vsm stride 72 (phase B c-free).
// =====================================================================
__global__ void __launch_bounds__(256, 2)
attn_tc(const float* __restrict__ lnw, const float* __restrict__ lnbp,
        float* __restrict__ out)
{
    const int bh = blockIdx.x;
    const int b  = bh >> 3;
    const int h  = bh & 7;

    extern __shared__ __align__(16) float sm[];
    float* ksm  = sm;                    // [200][KST]
    float* vsm  = ksm + 200 * KST;       // [200][VST]
    float* pool = vsm + 200 * VST;       // [8][64]
    float* lnsm = pool + 512;            // gamma[64], beta[64]

    const int tid  = threadIdx.x;
    const int lane = tid & 31, warp = tid >> 5;
    const int gid  = lane >> 2, tig = lane & 3;

    const float* kg = g_kv + ((size_t)b * 1024 + h * 64) * S2;
    const float* vg = g_kv + ((size_t)b * 1024 + 512 + h * 64) * S2;
    for (int idx = tid; idx < 200 * 64; idx += 256) {
        int j = idx % 200, d = idx / 200;
        ksm[j * KST + d] = (j < S2) ? kg[(size_t)d * S2 + j] : 0.f;
        vsm[j * VST + d] = (j < S2) ? vg[(size_t)d * S2 + j] : 0.f;
    }
    if (tid < 128) lnsm[tid] = (tid < 64) ? lnw[h * 64 + tid] : lnbp[h * 64 + tid - 64];
    __syncthreads();

    float pacc[16];
#pragma unroll
    for (int i = 0; i < 16; i++) pacc[i] = 0.f;

    const float* qg = g_q + ((size_t)b * INNER + h * 64) * HW;
    const float* rg = g_res + (size_t)b * DH * HW;

    const int srcLow  = (lane & ~3) | (tig >> 1);
    const int srcHigh = srcLow + 2;
    const bool odd = (tig & 1) != 0;

    for (int t = warp; t < 49; t += 8) {
        const int r0 = t * 16;

        float oacc[8][4];
#pragma unroll
        for (int nt = 0; nt < 8; nt++) {
            oacc[nt][0] = oacc[nt][1] = oacc[nt][2] = oacc[nt][3] = 0.f;
        }
        float mlo, mhi, llo, lhi;

        // ================= half 0: key tiles 0..12 =========
        {
            float sacc[13][4];
#pragma unroll
            for (int nt = 0; nt < 13; nt++) {
                sacc[nt][0] = sacc[nt][1] = sacc[nt][2] = sacc[nt][3] = 0.f;
            }
#pragma unroll
            for (int kk = 0; kk < 8; kk++) {
                const int d0 = kk * 8 + tig;
                uint32_t a[4];
                a[0] = __float_as_uint(qg[(size_t)d0 * HW + r0 + gid]);
                a[1] = __float_as_uint(qg[(size_t)d0 * HW + r0 + gid + 8]);
                a[2] = __float_as_uint(qg[(size_t)(d0 + 4) * HW + r0 + gid]);
                a[3] = __float_as_uint(qg[(size_t)(d0 + 4) * HW + r0 + gid + 8]);
#pragma unroll
                for (int nt = 0; nt < 13; nt++) {
                    uint32_t bfr[2];
                    bfr[0] = __float_as_uint(ksm[(nt * 8 + gid) * KST + d0]);
                    bfr[1] = __float_as_uint(ksm[(nt * 8 + gid) * KST + d0 + 4]);
                    mma_tf32(sacc[nt], a, bfr);
                }
            }
            mlo = -1e30f; mhi = -1e30f;
#pragma unroll
            for (int nt = 0; nt < 13; nt++) {
                mlo = fmaxf(mlo, fmaxf(sacc[nt][0], sacc[nt][1]));
                mhi = fmaxf(mhi, fmaxf(sacc[nt][2], sacc[nt][3]));
            }
            mlo = fmaxf(mlo, __shfl_xor_sync(0xffffffffu, mlo, 1));
            mlo = fmaxf(mlo, __shfl_xor_sync(0xffffffffu, mlo, 2));
            mhi = fmaxf(mhi, __shfl_xor_sync(0xffffffffu, mhi, 1));
            mhi = fmaxf(mhi, __shfl_xor_sync(0xffffffffu, mhi, 2));
            const float mls = mlo * ATTN_SCALE, mhs = mhi * ATTN_SCALE;
            llo = 0.f; lhi = 0.f;
#pragma unroll
            for (int nt = 0; nt < 13; nt++) {
                float e0 = __expf(fmaf(sacc[nt][0], ATTN_SCALE, -mls));
                float e1 = __expf(fmaf(sacc[nt][1], ATTN_SCALE, -mls));
                float e2 = __expf(fmaf(sacc[nt][2], ATTN_SCALE, -mhs));
                float e3 = __expf(fmaf(sacc[nt][3], ATTN_SCALE, -mhs));
                sacc[nt][0] = e0; sacc[nt][1] = e1; sacc[nt][2] = e2; sacc[nt][3] = e3;
                llo += e0 + e1; lhi += e2 + e3;
            }
            llo += __shfl_xor_sync(0xffffffffu, llo, 1);
            llo += __shfl_xor_sync(0xffffffffu, llo, 2);
            lhi += __shfl_xor_sync(0xffffffffu, lhi, 1);
            lhi += __shfl_xor_sync(0xffffffffu, lhi, 2);

#pragma unroll
            for (int kk = 0; kk < 13; kk++) {
                float u0 = __shfl_sync(0xffffffffu, sacc[kk][0], srcLow);
                float u1 = __shfl_sync(0xffffffffu, sacc[kk][1], srcLow);
                float w0 = __shfl_sync(0xffffffffu, sacc[kk][2], srcLow);
                float w1 = __shfl_sync(0xffffffffu, sacc[kk][3], srcLow);
                float v0 = __shfl_sync(0xffffffffu, sacc[kk][0], srcHigh);
                float v1 = __shfl_sync(0xffffffffu, sacc[kk][1], srcHigh);
                float z0 = __shfl_sync(0xffffffffu, sacc[kk][2], srcHigh);
                float z1 = __shfl_sync(0xffffffffu, sacc[kk][3], srcHigh);
                uint32_t a[4];
                a[0] = __float_as_uint(odd ? u1 : u0);
                a[1] = __float_as_uint(odd ? w1 : w0);
                a[2] = __float_as_uint(odd ? v1 : v0);
                a[3] = __float_as_uint(odd ? z1 : z0);
                const int j0 = kk * 8 + tig;
#pragma unroll
                for (int nt = 0; nt < 8; nt++) {
                    uint32_t bfr[2];
                    bfr[0] = __float_as_uint(vsm[j0 * VST + nt * 8 + gid]);
                    bfr[1] = __float_as_uint(vsm[(j0 + 4) * VST + nt * 8 + gid]);
                    mma_tf32(oacc[nt], a, bfr);
                }
            }
        }

        // ================= half 1: key tiles 13..24 ======
        {
            float sacc[12][4];
#pragma unroll
            for (int nt = 0; nt < 12; nt++) {
                sacc[nt][0] = sacc[nt][1] = sacc[nt][2] = sacc[nt][3] = 0.f;
            }
#pragma unroll
            for (int kk = 0; kk < 8; kk++) {
                const int d0 = kk * 8 + tig;
                uint32_t a[4];
                a[0] = __float_as_uint(qg[(size_t)d0 * HW + r0 + gid]);
                a[1] = __float_as_uint(qg[(size_t)d0 * HW + r0 + gid + 8]);
                a[2] = __float_as_uint(qg[(size_t)(d0 + 4) * HW + r0 + gid]);
                a[3] = __float_as_uint(qg[(size_t)(d0 + 4) * HW + r0 + gid + 8]);
#pragma unroll
                for (int nt = 0; nt < 12; nt++) {
                    uint32_t bfr[2];
                    bfr[0] = __float_as_uint(ksm[((13 + nt) * 8 + gid) * KST + d0]);
                    bfr[1] = __float_as_uint(ksm[((13 + nt) * 8 + gid) * KST + d0 + 4]);
                    mma_tf32(sacc[nt], a, bfr);
                }
            }
            if (tig >= 2) {
                sacc[11][0] = sacc[11][1] = sacc[11][2] = sacc[11][3] = -1e30f;
            }

            float m1lo = -1e30f, m1hi = -1e30f;
#pragma unroll
            for (int nt = 0; nt < 12; nt++) {
                m1lo = fmaxf(m1lo, fmaxf(sacc[nt][0], sacc[nt][1]));
                m1hi = fmaxf(m1hi, fmaxf(sacc[nt][2], sacc[nt][3]));
            }
            m1lo = fmaxf(m1lo, __shfl_xor_sync(0xffffffffu, m1lo, 1));
            m1lo = fmaxf(m1lo, __shfl_xor_sync(0xffffffffu, m1lo, 2));
            m1hi = fmaxf(m1hi, __shfl_xor_sync(0xffffffffu, m1hi, 1));
            m1hi = fmaxf(m1hi, __shfl_xor_sync(0xffffffffu, m1hi, 2));
            const float nmlo = fmaxf(mlo, m1lo), nmhi = fmaxf(mhi, m1hi);
            const float clo = __expf((mlo - nmlo) * ATTN_SCALE);
            const float chi = __expf((mhi - nmhi) * ATTN_SCALE);
            const float mls = nmlo * ATTN_SCALE, mhs = nmhi * ATTN_SCALE;
            float s1lo = 0.f, s1hi = 0.f;
#pragma unroll
            for (int nt = 0; nt < 12; nt++) {
                float e0 = __expf(fmaf(sacc[nt][0], ATTN_SCALE, -mls));
                float e1 = __expf(fmaf(sacc[nt][1], ATTN_SCALE, -mls));
                float e2 = __expf(fmaf(sacc[nt][2], ATTN_SCALE, -mhs));
                float e3 = __expf(fmaf(sacc[nt][3], ATTN_SCALE, -mhs));
                sacc[nt][0] = e0; sacc[nt][1] = e1; sacc[nt][2] = e2; sacc[nt][3] = e3;
                s1lo += e0 + e1; s1hi += e2 + e3;
            }
            s1lo += __shfl_xor_sync(0xffffffffu, s1lo, 1);
            s1lo += __shfl_xor_sync(0xffffffffu, s1lo, 2);
            s1hi += __shfl_xor_sync(0xffffffffu, s1hi, 1);
            s1hi += __shfl_xor_sync(0xffffffffu, s1hi, 2);
            llo = llo * clo + s1lo;
            lhi = lhi * chi + s1hi;
#pragma unroll
            for (int nt = 0; nt < 8; nt++) {
                oacc[nt][0] *= clo; oacc[nt][1] *= clo;
                oacc[nt][2] *= chi; oacc[nt][3] *= chi;
            }

#pragma unroll
            for (int kk = 0; kk < 12; kk++) {
                float u0 = __shfl_sync(0xffffffffu, sacc[kk][0], srcLow);
                float u1 = __shfl_sync(0xffffffffu, sacc[kk][1], srcLow);
                float w0 = __shfl_sync(0xffffffffu, sacc[kk][2], srcLow);
                float w1 = __shfl_sync(0xffffffffu, sacc[kk][3], srcLow);
                float v0 = __shfl_sync(0xffffffffu, sacc[kk][0], srcHigh);
                float v1 = __shfl_sync(0xffffffffu, sacc[kk][1], srcHigh);
                float z0 = __shfl_sync(0xffffffffu, sacc[kk][2], srcHigh);
                float z1 = __shfl_sync(0xffffffffu, sacc[kk][3], srcHigh);
                uint32_t a[4];
                a[0] = __float_as_uint(odd ? u1 : u0);
                a[1] = __float_as_uint(odd ? w1 : w0);
                a[2] = __float_as_uint(odd ? v1 : v0);
                a[3] = __float_as_uint(odd ? z1 : z0);
                const int j0 = (13 + kk) * 8 + tig;
#pragma unroll
                for (int nt = 0; nt < 8; nt++) {
                    uint32_t bfr[2];
                    bfr[0] = __float_as_uint(vsm[j0 * VST + nt * 8 + gid]);
                    bfr[1] = __float_as_uint(vsm[(j0 + 4) * VST + nt * 8 + gid]);
                    mma_tf32(oacc[nt], a, bfr);
                }
            }
        }

        // ---- epilogue: normalize + residual + LayerNorm + pool ----
        const float rlo2 = 1.f / llo, rhi2 = 1.f / lhi;
        float vlo[16], vhi[16];
        float slo2 = 0.f, shi2 = 0.f;
#pragma unroll
        for (int nt = 0; nt < 8; nt++)
#pragma unroll
            for (int c = 0; c < 2; c++) {
                const int i = nt * 2 + c;
                const int d = nt * 8 + 2 * tig + c;
                vlo[i] = oacc[nt][c]     * rlo2 + rg[(size_t)d * HW + r0 + gid];
                vhi[i] = oacc[nt][2 + c] * rhi2 + rg[(size_t)d * HW + r0 + gid + 8];
                slo2 += vlo[i]; shi2 += vhi[i];
            }
        slo2 += __shfl_xor_sync(0xffffffffu, slo2, 1);
        slo2 += __shfl_xor_sync(0xffffffffu, slo2, 2);
        shi2 += __shfl_xor_sync(0xffffffffu, shi2, 1);
        shi2 += __shfl_xor_sync(0xffffffffu, shi2, 2);
        const float mlo2 = slo2 * (1.f / 64.f), mhi2 = shi2 * (1.f / 64.f);
        float qlo = 0.f, qhi = 0.f;
#pragma unroll
        for (int i = 0; i < 16; i++) {
            float t1 = vlo[i] - mlo2; qlo += t1 * t1;
            float t2 = vhi[i] - mhi2; qhi += t2 * t2;
        }
        qlo += __shfl_xor_sync(0xffffffffu, qlo, 1);
        qlo += __shfl_xor_sync(0xffffffffu, qlo, 2);
        qhi += __shfl_xor_sync(0xffffffffu, qhi, 1);
        qhi += __shfl_xor_sync(0xffffffffu, qhi, 2);
        const float ilo = 1.f / (sqrtf(qlo * (1.f / 64.f)) + EPSF);
        const float ihi = 1.f / (sqrtf(qhi * (1.f / 64.f)) + EPSF);
#pragma unroll
        for (int nt = 0; nt < 8; nt++)
#pragma unroll
            for (int c = 0; c < 2; c++) {
                const int i = nt * 2 + c;
                const int d = nt * 8 + 2 * tig + c;
                const float lg = lnsm[d], lb = lnsm[64 + d];
                pacc[i] += (vlo[i] - mlo2) * ilo * lg + lb
                         + (vhi[i] - mhi2) * ihi * lg + lb;
            }
    }

#pragma unroll
    for (int i = 0; i < 16; i++) {
        pacc[i] += __shfl_xor_sync(0xffffffffu, pacc[i], 4);
        pacc[i] += __shfl_xor_sync(0xffffffffu, pacc[i], 8);
        pacc[i] += __shfl_xor_sync(0xffffffffu, pacc[i], 16);
    }
    if (gid == 0) {
#pragma unroll
        for (int nt = 0; nt < 8; nt++)
#pragma unroll
            for (int c = 0; c < 2; c++) {
                const int d = nt * 8 + 2 * tig + c;
                pool[warp * 64 + d] = pacc[nt * 2 + c];
            }
    }
    __syncthreads();
    if (tid < 64) {
        float s = 0.f;
#pragma unroll
        for (int w = 0; w < 8; w++) s += pool[w * 64 + tid];
        out[(size_t)bh * 64 + tid] = s * (1.f / 784.f);
    }
}

// =====================================================================
extern "C" void kernel_launch(void* const* d_in, const int* in_sizes, int n_in,
                              void* d_out, int out_size)
{
    const float* x      = (const float*)d_in[0];
    const float* w_dwq  = (const float*)d_in[1];
    const float* w_pwq  = (const float*)d_in[2];
    const float* w_dwkv = (const float*)d_in[3];
    const float* w_pwkv = (const float*)d_in[4];
    const float* w_ds   = (const float*)d_in[5];
    const float* ln_g   = (const float*)d_in[6];
    const float* ln_b   = (const float*)d_in[7];
    const float* bnq_g  = (const float*)d_in[8];
    const float* bnq_b  = (const float*)d_in[9];
    const float* bnq_m  = (const float*)d_in[10];
    const float* bnq_v  = (const float*)d_in[11];
    const float* bnkv_g = (const float*)d_in[12];
    const float* bnkv_b = (const float*)d_in[13];
    const float* bnkv_m = (const float*)d_in[14];
    const float* bnkv_v = (const float*)d_in[15];
    const float* bnds_g = (const float*)d_in[16];
    const float* bnds_b = (const float*)d_in[17];
    const float* bnds_m = (const float*)d_in[18];
    const float* bnds_v = (const float*)d_in[19];
    float* out = (float*)d_out;

    float *p_dwq, *p_dwkv, *p_q, *p_kv, *p_res, *p_wq, *p_wkv, *p_wds;
    cudaGetSymbolAddress((void**)&p_dwq,  g_dwq);
    cudaGetSymbolAddress((void**)&p_dwkv, g_dwkv);
    cudaGetSymbolAddress((void**)&p_q,    g_q);
    cudaGetSymbolAddress((void**)&p_kv,   g_kv);
    cudaGetSymbolAddress((void**)&p_res,  g_res);
    cudaGetSymbolAddress((void**)&p_wq,   g_wq);
    cudaGetSymbolAddress((void**)&p_wkv,  g_wkv);
    cudaGetSymbolAddress((void**)&p_wds,  g_wds);

    const int attn_smem = (200 * KST + 200 * VST + 512 + 128) * (int)sizeof(float); // 114560
    const int gemm_smem = GEMM_SMEM_FLOATS * (int)sizeof(float);                    // 53248

    static cudaStream_t s_side = nullptr;
    static cudaEvent_t ev_fork = nullptr, ev_prep = nullptr, ev_dw = nullptr, ev_join = nullptr;
    if (s_side == nullptr) {
        cudaStreamCreateWithFlags(&s_side, cudaStreamNonBlocking);
        cudaEventCreateWithFlags(&ev_fork, cudaEventDisableTiming);
        cudaEventCreateWithFlags(&ev_prep, cudaEventDisableTiming);
        cudaEventCreateWithFlags(&ev_dw,   cudaEventDisableTiming);
        cudaEventCreateWithFlags(&ev_join, cudaEventDisableTiming);
        cudaFuncSetAttribute(attn_tc,
                             cudaFuncAttributeMaxDynamicSharedMemorySize, attn_smem);
        cudaFuncSetAttribute(gemm_tc,
                             cudaFuncAttributeMaxDynamicSharedMemorySize, gemm_smem);
    }

    // ---- fork side stream
    cudaEventRecord(ev_fork, 0);
    cudaStreamWaitEvent(s_side, ev_fork, 0);

    // side: prep -> (ev_prep) -> residual gemm
    const int prep_total = PREP_Q_SZ + PREP_KV_SZ + PREP_DS_SZ;
    prep_all<<<(prep_total + 255) / 256, 256, 0, s_side>>>(w_pwq, w_pwkv, w_ds);
    cudaEventRecord(ev_prep, s_side);
    gemm_tc<<<dim3(13, 1, NB), 256, gemm_smem, s_side>>>(p_wds, x, p_res, 128, DH, HW, 0,
                                                         bnds_g, bnds_b, bnds_m, bnds_v);

    // main: dwconv -> (ev_dw)
    dwconv_fused<<<NB * NC, 256>>>(x, w_dwq, w_dwkv,
                                   bnq_g, bnq_b, bnq_m, bnq_v,
                                   bnkv_g, bnkv_b, bnkv_m, bnkv_v);
    cudaEventRecord(ev_dw, 0);

    // side: kv gemm (needs dwconv + prep) -> (ev_join)
    cudaStreamWaitEvent(s_side, ev_dw, 0);
    gemm_tc<<<dim3(4, 8, NB), 256, gemm_smem, s_side>>>(p_wkv, p_dwkv, p_kv, 1024, 2 * INNER, S2, 1,
                                                        nullptr, nullptr, nullptr, nullptr);
    cudaEventRecord(ev_join, s_side);

    // main: q gemm (needs dwconv [program order] + prep [event])
    cudaStreamWaitEvent(0, ev_prep, 0);
    gemm_tc<<<dim3(13, 4, NB), 256, gemm_smem>>>(p_wq, p_dwq, p_q, 512, INNER, HW, 1,
                                                 nullptr, nullptr, nullptr, nullptr);

    // join side (kv + res) before attention
    cudaStreamWaitEvent(0, ev_join, 0);
    attn_tc<<<NB * NHEADS, 256, attn_smem>>>(ln_g, ln_b, out);
}

// round 15
// speedup vs baseline: 1.2662x; 1.0086x over previous
#include <cuda_runtime.h>
#include <math.h>
#include <stdint.h>

#define NB      64
#define NC      640      // K of all GEMMs
#define HW      784      // 28*28
#define S2      196      // 14*14
#define NHEADS  8
#define DH      64
#define INNER   512      // NHEADS*DH
#define EPSF    1e-5f
#define ATTN_SCALE 0.125f
#define KST     68       // ksm stride (phase A conflict-free: 4*gid+tig)
#define VST     72       // vsm stride (phase B conflict-free: 8*tig+gid)

// ---------------- scratch (device globals; no allocation) ----------------
__device__ float g_dwq [NB * NC * HW];       // dwconv(s1)+BN (tf32-rounded)
__device__ float g_dwkv[NB * NC * S2];       // dwconv(s2)+BN (tf32-rounded)
__device__ float g_q   [NB * INNER * HW];    // q  [b][h*64+d][pos], tf32
__device__ float g_kv  [NB * 2 * INNER * S2];// tf32
__device__ float g_res [NB * DH * HW];       // residual [b][d][pos], fp32
__device__ float g_wq  [NC * 512];           // w_pwq^T  [k][m], tf32
__device__ float g_wkv [NC * 1024];          // w_pwkv^T [k][m], tf32
__device__ float g_wds [NC * 128];           // w_ds^T   [k][m], tf32, zero-padded to 128

// ---------------- helpers ----------------
__device__ __forceinline__ float to_tf32(float v) {
    uint32_t r;
    asm("cvt.rna.tf32.f32 %0, %1;" : "=r"(r) : "f"(v));
    return __uint_as_float(r);
}

__device__ __forceinline__ void cp16(uint32_t dst, const void* src, int src_bytes) {
    asm volatile("cp.async.cg.shared.global [%0], [%1], 16, %2;\n"
                 :: "r"(dst), "l"(src), "r"(src_bytes));
}

__device__ __forceinline__ void mma_tf32(float* c, const uint32_t* a, const uint32_t* b) {
    asm volatile(
        "mma.sync.aligned.m16n8k8.row.col.f32.tf32.tf32.f32 "
        "{%0,%1,%2,%3}, {%4,%5,%6,%7}, {%8,%9}, {%0,%1,%2,%3};\n"
        : "+f"(c[0]), "+f"(c[1]), "+f"(c[2]), "+f"(c[3])
        : "r"(a[0]), "r"(a[1]), "r"(a[2]), "r"(a[3]), "r"(b[0]), "r"(b[1]));
}

// =====================================================================
// Single prep kernel: transpose + tf32-round all three weight matrices.
// =====================================================================
#define PREP_Q_SZ   (NC * 512)
#define PREP_KV_SZ  (NC * 1024)
#define PREP_DS_SZ  (NC * 128)
__global__ void __launch_bounds__(256)
prep_all(const float* __restrict__ wq, const float* __restrict__ wkv,
         const float* __restrict__ wds)
{
    int idx = blockIdx.x * 256 + threadIdx.x;
    if (idx < PREP_Q_SZ) {
        int k = idx / 512, m = idx - k * 512;
        g_wq[idx] = to_tf32(wq[(size_t)m * NC + k]);
    } else if (idx < PREP_Q_SZ + PREP_KV_SZ) {
        int i = idx - PREP_Q_SZ;
        int k = i / 1024, m = i - k * 1024;
        g_wkv[i] = to_tf32(wkv[(size_t)m * NC + k]);
    } else if (idx < PREP_Q_SZ + PREP_KV_SZ + PREP_DS_SZ) {
        int i = idx - PREP_Q_SZ - PREP_KV_SZ;
        int k = i / 128, m = i - k * 128;
        g_wds[i] = (m < 64) ? to_tf32(wds[(size_t)m * NC + k]) : 0.f;
    }
}

// =====================================================================
// Fused depthwise conv (stride1 + stride2) + BN, per (b,c) block.
// =====================================================================
__global__ void __launch_bounds__(256)
dwconv_fused(const float* __restrict__ x,
             const float* __restrict__ wq, const float* __restrict__ wkv,
             const float* __restrict__ qg, const float* __restrict__ qb,
             const float* __restrict__ qm, const float* __restrict__ qvv,
             const float* __restrict__ kg, const float* __restrict__ kb,
             const float* __restrict__ km, const float* __restrict__ kvv)
{
    const int bc = blockIdx.x;
    const int c  = bc % NC;
    __shared__ float xs[30 * 30];
    const int tid = threadIdx.x;
    const int cx = tid & 31, ry = tid >> 5;

    if (tid < 116) {
        int idx;
        if (tid < 30)       idx = tid;
        else if (tid < 60)  idx = 29 * 30 + (tid - 30);
        else if (tid < 88)  idx = (tid - 60 + 1) * 30;
        else                idx = (tid - 88 + 1) * 30 + 29;
        xs[idx] = 0.f;
    }
    const float* xp = x + (size_t)bc * HW;
    if (cx < 28) {
        for (int r = ry; r < 28; r += 8)
            xs[(r + 1) * 30 + cx + 1] = xp[r * 28 + cx];
    }
    __syncthreads();

    float wq9[9], wk9[9];
#pragma unroll
    for (int i = 0; i < 9; i++) { wq9[i] = wq[c * 9 + i]; wk9[i] = wkv[c * 9 + i]; }

    const float sq  = qg[c] * rsqrtf(qvv[c] + EPSF);
    const float bq  = qb[c] - qm[c] * sq;
    const float skv = kg[c] * rsqrtf(kvv[c] + EPSF);
    const float bkv = kb[c] - km[c] * skv;

    if (cx < 28) {
        float* oq = g_dwq + (size_t)bc * HW;
        for (int r = ry; r < 28; r += 8) {
            const float* s = &xs[r * 30 + cx];
            float acc = s[0]*wq9[0] + s[1]*wq9[1] + s[2]*wq9[2]
                      + s[30]*wq9[3] + s[31]*wq9[4] + s[32]*wq9[5]
                      + s[60]*wq9[6] + s[61]*wq9[7] + s[62]*wq9[8];
            oq[r * 28 + cx] = to_tf32(acc * sq + bq);
        }
    }
    if (cx < 14) {
        float* okv = g_dwkv + (size_t)bc * S2;
        for (int r = ry; r < 14; r += 8) {
            const float* s = &xs[(r * 2) * 30 + cx * 2];
            float acc = s[0]*wk9[0] + s[1]*wk9[1] + s[2]*wk9[2]
                      + s[30]*wk9[3] + s[31]*wk9[4] + s[32]*wk9[5]
                      + s[60]*wk9[6] + s[61]*wk9[7] + s[62]*wk9[8];
            okv[r * 14 + cx] = to_tf32(acc * skv + bkv);
        }
    }
}

// =====================================================================
// tf32 tensor-core GEMM (R8 config: 128x64x32, 4 blocks/SM)
// =====================================================================
#define GEMM_SMEM_FLOATS (2 * (32 * 136 + 32 * 72))
__global__ void __launch_bounds__(256)
gemm_tc(const float* __restrict__ wT, const float* __restrict__ act,
        float* __restrict__ Cc, int Mpad, int M, int N, int round_out,
        const float* __restrict__ bg, const float* __restrict__ bb,
        const float* __restrict__ bm, const float* __restrict__ bv)
{
    extern __shared__ float sm[];
    const int tid  = threadIdx.x;
    const int lane = tid & 31, warp = tid >> 5;
    const int wm = (warp >> 1) * 32;
    const int wn = (warp & 1) * 32;
    const int n0 = blockIdx.x * 64;
    const int m0 = blockIdx.y * 128;
    const float* Ab = act + (size_t)blockIdx.z * NC * N;
    float*       Cb = Cc  + (size_t)blockIdx.z * (size_t)M * N;

    float acc[2][4][4];
#pragma unroll
    for (int i = 0; i < 2; i++)
#pragma unroll
        for (int j = 0; j < 4; j++)
#pragma unroll
            for (int l = 0; l < 4; l++) acc[i][j][l] = 0.f;

    const int a_k = tid >> 5, a_m4 = (tid & 31) * 4;
    const int b_k = tid >> 4, b_n4 = (tid & 15) * 4;

    auto load_tile = [&](int k0, int st) {
        float* As = sm + st * (32 * 136 + 32 * 72);
        float* Bs = As + 32 * 136;
#pragma unroll
        for (int i = 0; i < 4; i++) {
            int k = a_k + i * 8;
            uint32_t dst = (uint32_t)__cvta_generic_to_shared(&As[k * 136 + a_m4]);
            cp16(dst, wT + (size_t)(k0 + k) * Mpad + m0 + a_m4, 16);
        }
#pragma unroll
        for (int i = 0; i < 2; i++) {
            int k = b_k + i * 16;
            int col = n0 + b_n4;
            uint32_t dst = (uint32_t)__cvta_generic_to_shared(&Bs[k * 72 + b_n4]);
            cp16(dst, Ab + (size_t)(k0 + k) * N + col, (col < N) ? 16 : 0);
        }
        asm volatile("cp.async.commit_group;\n");
    };

    load_tile(0, 0);
    for (int t = 0; t < 20; t++) {
        const int st = t & 1;
        if (t < 19) {
            load_tile((t + 1) * 32, st ^ 1);
            asm volatile("cp.async.wait_group 1;\n");
        } else {
            asm volatile("cp.async.wait_group 0;\n");
        }
        __syncthreads();
        const float* As = sm + st * (32 * 136 + 32 * 72);
        const float* Bs = As + 32 * 136;
#pragma unroll
        for (int kk = 0; kk < 32; kk += 8) {
            uint32_t af[2][4], bf[4][2];
            const int kq   = kk + (lane & 3);
            const int mrow = wm + (lane >> 2);
            const int ncol = wn + (lane >> 2);
#pragma unroll
            for (int mt = 0; mt < 2; mt++) {
                af[mt][0] = __float_as_uint(As[kq * 136 + mrow + mt * 16]);
                af[mt][1] = __float_as_uint(As[kq * 136 + mrow + mt * 16 + 8]);
                af[mt][2] = __float_as_uint(As[(kq + 4) * 136 + mrow + mt * 16]);
                af[mt][3] = __float_as_uint(As[(kq + 4) * 136 + mrow + mt * 16 + 8]);
            }
#pragma unroll
            for (int nt = 0; nt < 4; nt++) {
                bf[nt][0] = __float_as_uint(Bs[kq * 72 + ncol + nt * 8]);
                bf[nt][1] = __float_as_uint(Bs[(kq + 4) * 72 + ncol + nt * 8]);
            }
#pragma unroll
            for (int mt = 0; mt < 2; mt++)
#pragma unroll
                for (int nt = 0; nt < 4; nt++)
                    mma_tf32(acc[mt][nt], af[mt], bf[nt]);
        }
        __syncthreads();
    }

    const bool has_bn = (bg != nullptr);
#pragma unroll
    for (int mt = 0; mt < 2; mt++) {
#pragma unroll
        for (int half = 0; half < 2; half++) {
            const int m = m0 + wm + mt * 16 + (lane >> 2) + half * 8;
            if (m >= M) continue;
            float sc = 1.f, bi = 0.f;
            if (has_bn) { sc = bg[m] * rsqrtf(bv[m] + EPSF); bi = bb[m] - bm[m] * sc; }
#pragma unroll
            for (int nt = 0; nt < 4; nt++) {
                const int n = n0 + wn + nt * 8 + 2 * (lane & 3);
                if (n < N) {
                    float2 v;
                    v.x = acc[mt][nt][half * 2 + 0] * sc + bi;
                    v.y = acc[mt][nt][half * 2 + 1] * sc + bi;
                    if (round_out) { v.x = to_tf32(v.x); v.y = to_tf32(v.y); }
                    *(float2*)&Cb[(size_t)m * N + n] = v;
                }
            }
        }
    }
}

// =====================================================================
// Tensor-core attention, flash two-half key split, 2 blocks/SM.
// bh0 = block offset (batch-half pipelining).
// =====================================================================
__global__ void __launch_bounds__(256, 2)
attn_tc(const float* __restrict__ lnw, const float* __restrict__ lnbp,
        float* __restrict__ out, int bh0)
{
    const int bh = blockIdx.x + bh0;
    const int b  = bh >> 3;
    const int h  = bh & 7;

    extern __shared__ __align__(16) float sm[];
    float* ksm  = sm;                    // [200][KST]
    float* vsm  = ksm + 200 * KST;       // [200][VST]
    float* pool = vsm + 200 * VST;       // [8][64]
    float* lnsm = pool + 512;            // gamma[64], beta[64]

    const int tid  = threadIdx.x;
    const int lane = tid & 31, warp = tid >> 5;
    const int gid  = lane >> 2, tig = lane & 3;

    const float* kg = g_kv + ((size_t)b * 1024 + h * 64) * S2;
    const float* vg = g_kv + ((size_t)b * 1024 + 512 + h * 64) * S2;
    for (int idx = tid; idx < 200 * 64; idx += 256) {
        int j = idx % 200, d = idx / 200;
        ksm[j * KST + d] = (j < S2) ? kg[(size_t)d * S2 + j] : 0.f;
        vsm[j * VST + d] = (j < S2) ? vg[(size_t)d * S2 + j] : 0.f;
    }
    if (tid < 128) lnsm[tid] = (tid < 64) ? lnw[h * 64 + tid] : lnbp[h * 64 + tid - 64];
    __syncthreads();

    float pacc[16];
#pragma unroll
    for (int i = 0; i < 16; i++) pacc[i] = 0.f;

    const float* qg = g_q + ((size_t)b * INNER + h * 64) * HW;
    const float* rg = g_res + (size_t)b * DH * HW;

    const int srcLow  = (lane & ~3) | (tig >> 1);
    const int srcHigh = srcLow + 2;
    const bool odd = (tig & 1) != 0;

    for (int t = warp; t < 49; t += 8) {
        const int r0 = t * 16;

        float oacc[8][4];
#pragma unroll
        for (int nt = 0; nt < 8; nt++) {
            oacc[nt][0] = oacc[nt][1] = oacc[nt][2] = oacc[nt][3] = 0.f;
        }
        float mlo, mhi, llo, lhi;

        // ================= half 0: key tiles 0..12 =========
        {
            float sacc[13][4];
#pragma unroll
            for (int nt = 0; nt < 13; nt++) {
                sacc[nt][0] = sacc[nt][1] = sacc[nt][2] = sacc[nt][3] = 0.f;
            }
#pragma unroll
            for (int kk = 0; kk < 8; kk++) {
                const int d0 = kk * 8 + tig;
                uint32_t a[4];
                a[0] = __float_as_uint(qg[(size_t)d0 * HW + r0 + gid]);
                a[1] = __float_as_uint(qg[(size_t)d0 * HW + r0 + gid + 8]);
                a[2] = __float_as_uint(qg[(size_t)(d0 + 4) * HW + r0 + gid]);
                a[3] = __float_as_uint(qg[(size_t)(d0 + 4) * HW + r0 + gid + 8]);
#pragma unroll
                for (int nt = 0; nt < 13; nt++) {
                    uint32_t bfr[2];
                    bfr[0] = __float_as_uint(ksm[(nt * 8 + gid) * KST + d0]);
                    bfr[1] = __float_as_uint(ksm[(nt * 8 + gid) * KST + d0 + 4]);
                    mma_tf32(sacc[nt], a, bfr);
                }
            }
            mlo = -1e30f; mhi = -1e30f;
#pragma unroll
            for (int nt = 0; nt < 13; nt++) {
                mlo = fmaxf(mlo, fmaxf(sacc[nt][0], sacc[nt][1]));
                mhi = fmaxf(mhi, fmaxf(sacc[nt][2], sacc[nt][3]));
            }
            mlo = fmaxf(mlo, __shfl_xor_sync(0xffffffffu, mlo, 1));
            mlo = fmaxf(mlo, __shfl_xor_sync(0xffffffffu, mlo, 2));
            mhi = fmaxf(mhi, __shfl_xor_sync(0xffffffffu, mhi, 1));
            mhi = fmaxf(mhi, __shfl_xor_sync(0xffffffffu, mhi, 2));
            const float mls = mlo * ATTN_SCALE, mhs = mhi * ATTN_SCALE;
            llo = 0.f; lhi = 0.f;
#pragma unroll
            for (int nt = 0; nt < 13; nt++) {
                float e0 = __expf(fmaf(sacc[nt][0], ATTN_SCALE, -mls));
                float e1 = __expf(fmaf(sacc[nt][1], ATTN_SCALE, -mls));
                float e2 = __expf(fmaf(sacc[nt][2], ATTN_SCALE, -mhs));
                float e3 = __expf(fmaf(sacc[nt][3], ATTN_SCALE, -mhs));
                sacc[nt][0] = e0; sacc[nt][1] = e1; sacc[nt][2] = e2; sacc[nt][3] = e3;
                llo += e0 + e1; lhi += e2 + e3;
            }
            llo += __shfl_xor_sync(0xffffffffu, llo, 1);
            llo += __shfl_xor_sync(0xffffffffu, llo, 2);
            lhi += __shfl_xor_sync(0xffffffffu, lhi, 1);
            lhi += __shfl_xor_sync(0xffffffffu, lhi, 2);

#pragma unroll
            for (int kk = 0; kk < 13; kk++) {
                float u0 = __shfl_sync(0xffffffffu, sacc[kk][0], srcLow);
                float u1 = __shfl_sync(0xffffffffu, sacc[kk][1], srcLow);
                float w0 = __shfl_sync(0xffffffffu, sacc[kk][2], srcLow);
                float w1 = __shfl_sync(0xffffffffu, sacc[kk][3], srcLow);
                float v0 = __shfl_sync(0xffffffffu, sacc[kk][0], srcHigh);
                float v1 = __shfl_sync(0xffffffffu, sacc[kk][1], srcHigh);
                float z0 = __shfl_sync(0xffffffffu, sacc[kk][2], srcHigh);
                float z1 = __shfl_sync(0xffffffffu, sacc[kk][3], srcHigh);
                uint32_t a[4];
                a[0] = __float_as_uint(odd ? u1 : u0);
                a[1] = __float_as_uint(odd ? w1 : w0);
                a[2] = __float_as_uint(odd ? v1 : v0);
                a[3] = __float_as_uint(odd ? z1 : z0);
                const int j0 = kk * 8 + tig;
#pragma unroll
                for (int nt = 0; nt < 8; nt++) {
                    uint32_t bfr[2];
                    bfr[0] = __float_as_uint(vsm[j0 * VST + nt * 8 + gid]);
                    bfr[1] = __float_as_uint(vsm[(j0 + 4) * VST + nt * 8 + gid]);
                    mma_tf32(oacc[nt], a, bfr);
                }
            }
        }

        // ================= half 1: key tiles 13..24 ======
        {
            float sacc[12][4];
#pragma unroll
            for (int nt = 0; nt < 12; nt++) {
                sacc[nt][0] = sacc[nt][1] = sacc[nt][2] = sacc[nt][3] = 0.f;
            }
#pragma unroll
            for (int kk = 0; kk < 8; kk++) {
                const int d0 = kk * 8 + tig;
                uint32_t a[4];
                a[0] = __float_as_uint(qg[(size_t)d0 * HW + r0 + gid]);
                a[1] = __float_as_uint(qg[(size_t)d0 * HW + r0 + gid + 8]);
                a[2] = __float_as_uint(qg[(size_t)(d0 + 4) * HW + r0 + gid]);
                a[3] = __float_as_uint(qg[(size_t)(d0 + 4) * HW + r0 + gid + 8]);
#pragma unroll
                for (int nt = 0; nt < 12; nt++) {
                    uint32_t bfr[2];
                    bfr[0] = __float_as_uint(ksm[((13 + nt) * 8 + gid) * KST + d0]);
                    bfr[1] = __float_as_uint(ksm[((13 + nt) * 8 + gid) * KST + d0 + 4]);
                    mma_tf32(sacc[nt], a, bfr);
                }
            }
            if (tig >= 2) {
                sacc[11][0] = sacc[11][1] = sacc[11][2] = sacc[11][3] = -1e30f;
            }

            float m1lo = -1e30f, m1hi = -1e30f;
#pragma unroll
            for (int nt = 0; nt < 12; nt++) {
                m1lo = fmaxf(m1lo, fmaxf(sacc[nt][0], sacc[nt][1]));
                m1hi = fmaxf(m1hi, fmaxf(sacc[nt][2], sacc[nt][3]));
            }
            m1lo = fmaxf(m1lo, __shfl_xor_sync(0xffffffffu, m1lo, 1));
            m1lo = fmaxf(m1lo, __shfl_xor_sync(0xffffffffu, m1lo, 2));
            m1hi = fmaxf(m1hi, __shfl_xor_sync(0xffffffffu, m1hi, 1));
            m1hi = fmaxf(m1hi, __shfl_xor_sync(0xffffffffu, m1hi, 2));
            const float nmlo = fmaxf(mlo, m1lo), nmhi = fmaxf(mhi, m1hi);
            const float clo = __expf((mlo - nmlo) * ATTN_SCALE);
            const float chi = __expf((mhi - nmhi) * ATTN_SCALE);
            const float mls = nmlo * ATTN_SCALE, mhs = nmhi * ATTN_SCALE;
            float s1lo = 0.f, s1hi = 0.f;
#pragma unroll
            for (int nt = 0; nt < 12; nt++) {
                float e0 = __expf(fmaf(sacc[nt][0], ATTN_SCALE, -mls));
                float e1 = __expf(fmaf(sacc[nt][1], ATTN_SCALE, -mls));
                float e2 = __expf(fmaf(sacc[nt][2], ATTN_SCALE, -mhs));
                float e3 = __expf(fmaf(sacc[nt][3], ATTN_SCALE, -mhs));
                sacc[nt][0] = e0; sacc[nt][1] = e1; sacc[nt][2] = e2; sacc[nt][3] = e3;
                s1lo += e0 + e1; s1hi += e2 + e3;
            }
            s1lo += __shfl_xor_sync(0xffffffffu, s1lo, 1);
            s1lo += __shfl_xor_sync(0xffffffffu, s1lo, 2);
            s1hi += __shfl_xor_sync(0xffffffffu, s1hi, 1);
            s1hi += __shfl_xor_sync(0xffffffffu, s1hi, 2);
            llo = llo * clo + s1lo;
            lhi = lhi * chi + s1hi;
#pragma unroll
            for (int nt = 0; nt < 8; nt++) {
                oacc[nt][0] *= clo; oacc[nt][1] *= clo;
                oacc[nt][2] *= chi; oacc[nt][3] *= chi;
            }

#pragma unroll
            for (int kk = 0; kk < 12; kk++) {
                float u0 = __shfl_sync(0xffffffffu, sacc[kk][0], srcLow);
                float u1 = __shfl_sync(0xffffffffu, sacc[kk][1], srcLow);
                float w0 = __shfl_sync(0xffffffffu, sacc[kk][2], srcLow);
                float w1 = __shfl_sync(0xffffffffu, sacc[kk][3], srcLow);
                float v0 = __shfl_sync(0xffffffffu, sacc[kk][0], srcHigh);
                float v1 = __shfl_sync(0xffffffffu, sacc[kk][1], srcHigh);
                float z0 = __shfl_sync(0xffffffffu, sacc[kk][2], srcHigh);
                float z1 = __shfl_sync(0xffffffffu, sacc[kk][3], srcHigh);
                uint32_t a[4];
                a[0] = __float_as_uint(odd ? u1 : u0);
                a[1] = __float_as_uint(odd ? w1 : w0);
                a[2] = __float_as_uint(odd ? v1 : v0);
                a[3] = __float_as_uint(odd ? z1 : z0);
                const int j0 = (13 + kk) * 8 + tig;
#pragma unroll
                for (int nt = 0; nt < 8; nt++) {
                    uint32_t bfr[2];
                    bfr[0] = __float_as_uint(vsm[j0 * VST + nt * 8 + gid]);
                    bfr[1] = __float_as_uint(vsm[(j0 + 4) * VST + nt * 8 + gid]);
                    mma_tf32(oacc[nt], a, bfr);
                }
            }
        }

        // ---- epilogue: normalize + residual + LayerNorm + pool ----
        const float rlo2 = 1.f / llo, rhi2 = 1.f / lhi;
        float vlo[16], vhi[16];
        float slo2 = 0.f, shi2 = 0.f;
#pragma unroll
        for (int nt = 0; nt < 8; nt++)
#pragma unroll
            for (int c = 0; c < 2; c++) {
                const int i = nt * 2 + c;
                const int d = nt * 8 + 2 * tig + c;
                vlo[i] = oacc[nt][c]     * rlo2 + rg[(size_t)d * HW + r0 + gid];
                vhi[i] = oacc[nt][2 + c] * rhi2 + rg[(size_t)d * HW + r0 + gid + 8];
                slo2 += vlo[i]; shi2 += vhi[i];
            }
        slo2 += __shfl_xor_sync(0xffffffffu, slo2, 1);
        slo2 += __shfl_xor_sync(0xffffffffu, slo2, 2);
        shi2 += __shfl_xor_sync(0xffffffffu, shi2, 1);
        shi2 += __shfl_xor_sync(0xffffffffu, shi2, 2);
        const float mlo2 = slo2 * (1.f / 64.f), mhi2 = shi2 * (1.f / 64.f);
        float qlo = 0.f, qhi = 0.f;
#pragma unroll
        for (int i = 0; i < 16; i++) {
            float t1 = vlo[i] - mlo2; qlo += t1 * t1;
            float t2 = vhi[i] - mhi2; qhi += t2 * t2;
        }
        qlo += __shfl_xor_sync(0xffffffffu, qlo, 1);
        qlo += __shfl_xor_sync(0xffffffffu, qlo, 2);
        qhi += __shfl_xor_sync(0xffffffffu, qhi, 1);
        qhi += __shfl_xor_sync(0xffffffffu, qhi, 2);
        const float ilo = 1.f / (sqrtf(qlo * (1.f / 64.f)) + EPSF);
        const float ihi = 1.f / (sqrtf(qhi * (1.f / 64.f)) + EPSF);
#pragma unroll
        for (int nt = 0; nt < 8; nt++)
#pragma unroll
            for (int c = 0; c < 2; c++) {
                const int i = nt * 2 + c;
                const int d = nt * 8 + 2 * tig + c;
                const float lg = lnsm[d], lb = lnsm[64 + d];
                pacc[i] += (vlo[i] - mlo2) * ilo * lg + lb
                         + (vhi[i] - mhi2) * ihi * lg + lb;
            }
    }

#pragma unroll
    for (int i = 0; i < 16; i++) {
        pacc[i] += __shfl_xor_sync(0xffffffffu, pacc[i], 4);
        pacc[i] += __shfl_xor_sync(0xffffffffu, pacc[i], 8);
        pacc[i] += __shfl_xor_sync(0xffffffffu, pacc[i], 16);
    }
    if (gid == 0) {
#pragma unroll
        for (int nt = 0; nt < 8; nt++)
#pragma unroll
            for (int c = 0; c < 2; c++) {
                const int d = nt * 8 + 2 * tig + c;
                pool[warp * 64 + d] = pacc[nt * 2 + c];
            }
    }
    __syncthreads();
    if (tid < 64) {
        float s = 0.f;
#pragma unroll
        for (int w = 0; w < 8; w++) s += pool[w * 64 + tid];
        out[(size_t)bh * 64 + tid] = s * (1.f / 784.f);
    }
}

// =====================================================================
extern "C" void kernel_launch(void* const* d_in, const int* in_sizes, int n_in,
                              void* d_out, int out_size)
{
    const float* x      = (const float*)d_in[0];
    const float* w_dwq  = (const float*)d_in[1];
    const float* w_pwq  = (const float*)d_in[2];
    const float* w_dwkv = (const float*)d_in[3];
    const float* w_pwkv = (const float*)d_in[4];
    const float* w_ds   = (const float*)d_in[5];
    const float* ln_g   = (const float*)d_in[6];
    const float* ln_b   = (const float*)d_in[7];
    const float* bnq_g  = (const float*)d_in[8];
    const float* bnq_b  = (const float*)d_in[9];
    const float* bnq_m  = (const float*)d_in[10];
    const float* bnq_v  = (const float*)d_in[11];
    const float* bnkv_g = (const float*)d_in[12];
    const float* bnkv_b = (const float*)d_in[13];
    const float* bnkv_m = (const float*)d_in[14];
    const float* bnkv_v = (const float*)d_in[15];
    const float* bnds_g = (const float*)d_in[16];
    const float* bnds_b = (const float*)d_in[17];
    const float* bnds_m = (const float*)d_in[18];
    const float* bnds_v = (const float*)d_in[19];
    float* out = (float*)d_out;

    float *p_dwq, *p_dwkv, *p_q, *p_kv, *p_res, *p_wq, *p_wkv, *p_wds;
    cudaGetSymbolAddress((void**)&p_dwq,  g_dwq);
    cudaGetSymbolAddress((void**)&p_dwkv, g_dwkv);
    cudaGetSymbolAddress((void**)&p_q,    g_q);
    cudaGetSymbolAddress((void**)&p_kv,   g_kv);
    cudaGetSymbolAddress((void**)&p_res,  g_res);
    cudaGetSymbolAddress((void**)&p_wq,   g_wq);
    cudaGetSymbolAddress((void**)&p_wkv,  g_wkv);
    cudaGetSymbolAddress((void**)&p_wds,  g_wds);

    const int attn_smem = (200 * KST + 200 * VST + 512 + 128) * (int)sizeof(float); // 114560
    const int gemm_smem = GEMM_SMEM_FLOATS * (int)sizeof(float);                    // 53248

    static cudaStream_t s_side = nullptr;
    static cudaEvent_t ev_fork = nullptr, ev_prep = nullptr, ev_dw = nullptr;
    static cudaEvent_t ev_q0 = nullptr, ev_kv = nullptr, ev_join = nullptr;
    if (s_side == nullptr) {
        cudaStreamCreateWithFlags(&s_side, cudaStreamNonBlocking);
        cudaEventCreateWithFlags(&ev_fork, cudaEventDisableTiming);
        cudaEventCreateWithFlags(&ev_prep, cudaEventDisableTiming);
        cudaEventCreateWithFlags(&ev_dw,   cudaEventDisableTiming);
        cudaEventCreateWithFlags(&ev_q0,   cudaEventDisableTiming);
        cudaEventCreateWithFlags(&ev_kv,   cudaEventDisableTiming);
        cudaEventCreateWithFlags(&ev_join, cudaEventDisableTiming);
        cudaFuncSetAttribute(attn_tc,
                             cudaFuncAttributeMaxDynamicSharedMemorySize, attn_smem);
        cudaFuncSetAttribute(gemm_tc,
                             cudaFuncAttributeMaxDynamicSharedMemorySize, gemm_smem);
    }

    const int HB = NB / 2;  // 32 batches per pipeline half

    // ---- fork side stream
    cudaEventRecord(ev_fork, 0);
    cudaStreamWaitEvent(s_side, ev_fork, 0);

    // side: prep -> ev_prep -> residual gemm
    const int prep_total = PREP_Q_SZ + PREP_KV_SZ + PREP_DS_SZ;
    prep_all<<<(prep_total + 255) / 256, 256, 0, s_side>>>(w_pwq, w_pwkv, w_ds);
    cudaEventRecord(ev_prep, s_side);
    gemm_tc<<<dim3(13, 1, NB), 256, gemm_smem, s_side>>>(p_wds, x, p_res, 128, DH, HW, 0,
                                                         bnds_g, bnds_b, bnds_m, bnds_v);

    // main: dwconv -> ev_dw
    dwconv_fused<<<NB * NC, 256>>>(x, w_dwq, w_dwkv,
                                   bnq_g, bnq_b, bnq_m, bnq_v,
                                   bnkv_g, bnkv_b, bnkv_m, bnkv_v);
    cudaEventRecord(ev_dw, 0);

    // side: kv gemm (needs dwconv + prep) -> ev_kv
    cudaStreamWaitEvent(s_side, ev_dw, 0);
    gemm_tc<<<dim3(4, 8, NB), 256, gemm_smem, s_side>>>(p_wkv, p_dwkv, p_kv, 1024, 2 * INNER, S2, 1,
                                                        nullptr, nullptr, nullptr, nullptr);
    cudaEventRecord(ev_kv, s_side);

    // main: q gemm half 0 (batches 0..31) -> ev_q0
    cudaStreamWaitEvent(0, ev_prep, 0);
    gemm_tc<<<dim3(13, 4, HB), 256, gemm_smem>>>(p_wq, p_dwq, p_q, 512, INNER, HW, 1,
                                                 nullptr, nullptr, nullptr, nullptr);
    cudaEventRecord(ev_q0, 0);

    // side: attn half 0 (bh 0..255; needs q half0 + kv + res) -> ev_join
    cudaStreamWaitEvent(s_side, ev_q0, 0);
    attn_tc<<<HB * NHEADS, 256, attn_smem, s_side>>>(ln_g, ln_b, out, 0);
    cudaEventRecord(ev_join, s_side);

    // main: q gemm half 1 (batches 32..63)
    gemm_tc<<<dim3(13, 4, HB), 256, gemm_smem>>>(p_wq,
                                                 p_dwq + (size_t)HB * NC * HW,
                                                 p_q   + (size_t)HB * INNER * HW,
                                                 512, INNER, HW, 1,
                                                 nullptr, nullptr, nullptr, nullptr);

    // main: attn half 1 (needs q half1 [program order] + kv + res [ev_kv])
    cudaStreamWaitEvent(0, ev_kv, 0);
    attn_tc<<<HB * NHEADS, 256, attn_smem>>>(ln_g, ln_b, out, HB * NHEADS);

    // join side (attn half 0) into main before return
    cudaStreamWaitEvent(0, ev_join, 0);
}

// round 16
// speedup vs baseline: 1.2805x; 1.0113x over previous
#include <cuda_runtime.h>
#include <math.h>
#include <stdint.h>

#define NB      64
#define NC      640      // K of all GEMMs
#define HW      784      // 28*28
#define S2      196      // 14*14
#define NHEADS  8
#define DH      64
#define INNER   512      // NHEADS*DH
#define EPSF    1e-5f
#define ATTN_SCALE 0.125f
#define KST     68       // ksm stride (phase A conflict-free: 4*gid+tig)
#define VST     72       // vsm stride (phase B conflict-free: 8*tig+gid)

// ---------------- scratch (device globals; no allocation) ----------------
__device__ float g_dwq [NB * NC * HW];       // dwconv(s1)+BN (tf32-rounded)
__device__ float g_dwkv[NB * NC * S2];       // dwconv(s2)+BN (tf32-rounded)
__device__ float g_q   [NB * INNER * HW];    // q  [b][h*64+d][pos], tf32
__device__ float g_kv  [NB * 2 * INNER * S2];// tf32
__device__ float g_res [NB * DH * HW];       // residual [b][d][pos], fp32
__device__ float g_wq  [NC * 512];           // w_pwq^T  [k][m], tf32
__device__ float g_wkv [NC * 1024];          // w_pwkv^T [k][m], tf32
__device__ float g_wds [NC * 128];           // w_ds^T   [k][m], tf32, zero-padded to 128

// ---------------- helpers ----------------
__device__ __forceinline__ float to_tf32(float v) {
    uint32_t r;
    asm("cvt.rna.tf32.f32 %0, %1;" : "=r"(r) : "f"(v));
    return __uint_as_float(r);
}

__device__ __forceinline__ void cp16(uint32_t dst, const void* src, int src_bytes) {
    asm volatile("cp.async.cg.shared.global [%0], [%1], 16, %2;\n"
                 :: "r"(dst), "l"(src), "r"(src_bytes));
}

__device__ __forceinline__ void mma_tf32(float* c, const uint32_t* a, const uint32_t* b) {
    asm volatile(
        "mma.sync.aligned.m16n8k8.row.col.f32.tf32.tf32.f32 "
        "{%0,%1,%2,%3}, {%4,%5,%6,%7}, {%8,%9}, {%0,%1,%2,%3};\n"
        : "+f"(c[0]), "+f"(c[1]), "+f"(c[2]), "+f"(c[3])
        : "r"(a[0]), "r"(a[1]), "r"(a[2]), "r"(a[3]), "r"(b[0]), "r"(b[1]));
}

// =====================================================================
// Single prep kernel: transpose + tf32-round all three weight matrices.
// =====================================================================
#define PREP_Q_SZ   (NC * 512)
#define PREP_KV_SZ  (NC * 1024)
#define PREP_DS_SZ  (NC * 128)
__global__ void __launch_bounds__(256)
prep_all(const float* __restrict__ wq, const float* __restrict__ wkv,
         const float* __restrict__ wds)
{
    int idx = blockIdx.x * 256 + threadIdx.x;
    if (idx < PREP_Q_SZ) {
        int k = idx / 512, m = idx - k * 512;
        g_wq[idx] = to_tf32(wq[(size_t)m * NC + k]);
    } else if (idx < PREP_Q_SZ + PREP_KV_SZ) {
        int i = idx - PREP_Q_SZ;
        int k = i / 1024, m = i - k * 1024;
        g_wkv[i] = to_tf32(wkv[(size_t)m * NC + k]);
    } else if (idx < PREP_Q_SZ + PREP_KV_SZ + PREP_DS_SZ) {
        int i = idx - PREP_Q_SZ - PREP_KV_SZ;
        int k = i / 128, m = i - k * 128;
        g_wds[i] = (m < 64) ? to_tf32(wds[(size_t)m * NC + k]) : 0.f;
    }
}

// =====================================================================
// Fused depthwise conv (stride1 + stride2) + BN, per (b,c) block.
// bc0 = block offset (batch-half pipelining).
// =====================================================================
__global__ void __launch_bounds__(256)
dwconv_fused(const float* __restrict__ x,
             const float* __restrict__ wq, const float* __restrict__ wkv,
             const float* __restrict__ qg, const float* __restrict__ qb,
             const float* __restrict__ qm, const float* __restrict__ qvv,
             const float* __restrict__ kg, const float* __restrict__ kb,
             const float* __restrict__ km, const float* __restrict__ kvv,
             int bc0)
{
    const int bc = blockIdx.x + bc0;
    const int c  = bc % NC;
    __shared__ float xs[30 * 30];
    const int tid = threadIdx.x;
    const int cx = tid & 31, ry = tid >> 5;

    if (tid < 116) {
        int idx;
        if (tid < 30)       idx = tid;
        else if (tid < 60)  idx = 29 * 30 + (tid - 30);
        else if (tid < 88)  idx = (tid - 60 + 1) * 30;
        else                idx = (tid - 88 + 1) * 30 + 29;
        xs[idx] = 0.f;
    }
    const float* xp = x + (size_t)bc * HW;
    if (cx < 28) {
        for (int r = ry; r < 28; r += 8)
            xs[(r + 1) * 30 + cx + 1] = xp[r * 28 + cx];
    }
    __syncthreads();

    float wq9[9], wk9[9];
#pragma unroll
    for (int i = 0; i < 9; i++) { wq9[i] = wq[c * 9 + i]; wk9[i] = wkv[c * 9 + i]; }

    const float sq  = qg[c] * rsqrtf(qvv[c] + EPSF);
    const float bq  = qb[c] - qm[c] * sq;
    const float skv = kg[c] * rsqrtf(kvv[c] + EPSF);
    const float bkv = kb[c] - km[c] * skv;

    if (cx < 28) {
        float* oq = g_dwq + (size_t)bc * HW;
        for (int r = ry; r < 28; r += 8) {
            const float* s = &xs[r * 30 + cx];
            float acc = s[0]*wq9[0] + s[1]*wq9[1] + s[2]*wq9[2]
                      + s[30]*wq9[3] + s[31]*wq9[4] + s[32]*wq9[5]
                      + s[60]*wq9[6] + s[61]*wq9[7] + s[62]*wq9[8];
            oq[r * 28 + cx] = to_tf32(acc * sq + bq);
        }
    }
    if (cx < 14) {
        float* okv = g_dwkv + (size_t)bc * S2;
        for (int r = ry; r < 14; r += 8) {
            const float* s = &xs[(r * 2) * 30 + cx * 2];
            float acc = s[0]*wk9[0] + s[1]*wk9[1] + s[2]*wk9[2]
                      + s[30]*wk9[3] + s[31]*wk9[4] + s[32]*wk9[5]
                      + s[60]*wk9[6] + s[61]*wk9[7] + s[62]*wk9[8];
            okv[r * 14 + cx] = to_tf32(acc * skv + bkv);
        }
    }
}

// =====================================================================
// tf32 tensor-core GEMM (R8 config: 128x64x32, 4 blocks/SM)
// =====================================================================
#define GEMM_SMEM_FLOATS (2 * (32 * 136 + 32 * 72))
__global__ void __launch_bounds__(256)
gemm_tc(const float* __restrict__ wT, const float* __restrict__ act,
        float* __restrict__ Cc, int Mpad, int M, int N, int round_out,
        const float* __restrict__ bg, const float* __restrict__ bb,
        const float* __restrict__ bm, const float* __restrict__ bv)
{
    extern __shared__ float sm[];
    const int tid  = threadIdx.x;
    const int lane = tid & 31, warp = tid >> 5;
    const int wm = (warp >> 1) * 32;
    const int wn = (warp & 1) * 32;
    const int n0 = blockIdx.x * 64;
    const int m0 = blockIdx.y * 128;
    const float* Ab = act + (size_t)blockIdx.z * NC * N;
    float*       Cb = Cc  + (size_t)blockIdx.z * (size_t)M * N;

    float acc[2][4][4];
#pragma unroll
    for (int i = 0; i < 2; i++)
#pragma unroll
        for (int j = 0; j < 4; j++)
#pragma unroll
            for (int l = 0; l < 4; l++) acc[i][j][l] = 0.f;

    const int a_k = tid >> 5, a_m4 = (tid & 31) * 4;
    const int b_k = tid >> 4, b_n4 = (tid & 15) * 4;

    auto load_tile = [&](int k0, int st) {
        float* As = sm + st * (32 * 136 + 32 * 72);
        float* Bs = As + 32 * 136;
#pragma unroll
        for (int i = 0; i < 4; i++) {
            int k = a_k + i * 8;
            uint32_t dst = (uint32_t)__cvta_generic_to_shared(&As[k * 136 + a_m4]);
            cp16(dst, wT + (size_t)(k0 + k) * Mpad + m0 + a_m4, 16);
        }
#pragma unroll
        for (int i = 0; i < 2; i++) {
            int k = b_k + i * 16;
            int col = n0 + b_n4;
            uint32_t dst = (uint32_t)__cvta_generic_to_shared(&Bs[k * 72 + b_n4]);
            cp16(dst, Ab + (size_t)(k0 + k) * N + col, (col < N) ? 16 : 0);
        }
        asm volatile("cp.async.commit_group;\n");
    };

    load_tile(0, 0);
    for (int t = 0; t < 20; t++) {
        const int st = t & 1;
        if (t < 19) {
            load_tile((t + 1) * 32, st ^ 1);
            asm volatile("cp.async.wait_group 1;\n");
        } else {
            asm volatile("cp.async.wait_group 0;\n");
        }
        __syncthreads();
        const float* As = sm + st * (32 * 136 + 32 * 72);
        const float* Bs = As + 32 * 136;
#pragma unroll
        for (int kk = 0; kk < 32; kk += 8) {
            uint32_t af[2][4], bf[4][2];
            const int kq   = kk + (lane & 3);
            const int mrow = wm + (lane >> 2);
            const int ncol = wn + (lane >> 2);
#pragma unroll
            for (int mt = 0; mt < 2; mt++) {
                af[mt][0] = __float_as_uint(As[kq * 136 + mrow + mt * 16]);
                af[mt][1] = __float_as_uint(As[kq * 136 + mrow + mt * 16 + 8]);
                af[mt][2] = __float_as_uint(As[(kq + 4) * 136 + mrow + mt * 16]);
                af[mt][3] = __float_as_uint(As[(kq + 4) * 136 + mrow + mt * 16 + 8]);
            }
#pragma unroll
            for (int nt = 0; nt < 4; nt++) {
                bf[nt][0] = __float_as_uint(Bs[kq * 72 + ncol + nt * 8]);
                bf[nt][1] = __float_as_uint(Bs[(kq + 4) * 72 + ncol + nt * 8]);
            }
#pragma unroll
            for (int mt = 0; mt < 2; mt++)
#pragma unroll
                for (int nt = 0; nt < 4; nt++)
                    mma_tf32(acc[mt][nt], af[mt], bf[nt]);
        }
        __syncthreads();
    }

    const bool has_bn = (bg != nullptr);
#pragma unroll
    for (int mt = 0; mt < 2; mt++) {
#pragma unroll
        for (int half = 0; half < 2; half++) {
            const int m = m0 + wm + mt * 16 + (lane >> 2) + half * 8;
            if (m >= M) continue;
            float sc = 1.f, bi = 0.f;
            if (has_bn) { sc = bg[m] * rsqrtf(bv[m] + EPSF); bi = bb[m] - bm[m] * sc; }
#pragma unroll
            for (int nt = 0; nt < 4; nt++) {
                const int n = n0 + wn + nt * 8 + 2 * (lane & 3);
                if (n < N) {
                    float2 v;
                    v.x = acc[mt][nt][half * 2 + 0] * sc + bi;
                    v.y = acc[mt][nt][half * 2 + 1] * sc + bi;
                    if (round_out) { v.x = to_tf32(v.x); v.y = to_tf32(v.y); }
                    *(float2*)&Cb[(size_t)m * N + n] = v;
                }
            }
        }
    }
}

// =====================================================================
// Tensor-core attention, flash two-half key split, 2 blocks/SM.
// bh0 = block offset (batch-half pipelining).
// =====================================================================
__global__ void __launch_bounds__(256, 2)
attn_tc(const float* __restrict__ lnw, const float* __restrict__ lnbp,
        float* __restrict__ out, int bh0)
{
    const int bh = blockIdx.x + bh0;
    const int b  = bh >> 3;
    const int h  = bh & 7;

    extern __shared__ __align__(16) float sm[];
    float* ksm  = sm;                    // [200][KST]
    float* vsm  = ksm + 200 * KST;       // [200][VST]
    float* pool = vsm + 200 * VST;       // [8][64]
    float* lnsm = pool + 512;            // gamma[64], beta[64]

    const int tid  = threadIdx.x;
    const int lane = tid & 31, warp = tid >> 5;
    const int gid  = lane >> 2, tig = lane & 3;

    const float* kg = g_kv + ((size_t)b * 1024 + h * 64) * S2;
    const float* vg = g_kv + ((size_t)b * 1024 + 512 + h * 64) * S2;
    for (int idx = tid; idx < 200 * 64; idx += 256) {
        int j = idx % 200, d = idx / 200;
        ksm[j * KST + d] = (j < S2) ? kg[(size_t)d * S2 + j] : 0.f;
        vsm[j * VST + d] = (j < S2) ? vg[(size_t)d * S2 + j] : 0.f;
    }
    if (tid < 128) lnsm[tid] = (tid < 64) ? lnw[h * 64 + tid] : lnbp[h * 64 + tid - 64];
    __syncthreads();

    float pacc[16];
#pragma unroll
    for (int i = 0; i < 16; i++) pacc[i] = 0.f;

    const float* qg = g_q + ((size_t)b * INNER + h * 64) * HW;
    const float* rg = g_res + (size_t)b * DH * HW;

    const int srcLow  = (lane & ~3) | (tig >> 1);
    const int srcHigh = srcLow + 2;
    const bool odd = (tig & 1) != 0;

    for (int t = warp; t < 49; t += 8) {
        const int r0 = t * 16;

        float oacc[8][4];
#pragma unroll
        for (int nt = 0; nt < 8; nt++) {
            oacc[nt][0] = oacc[nt][1] = oacc[nt][2] = oacc[nt][3] = 0.f;
        }
        float mlo, mhi, llo, lhi;

        // ================= half 0: key tiles 0..12 =========
        {
            float sacc[13][4];
#pragma unroll
            for (int nt = 0; nt < 13; nt++) {
                sacc[nt][0] = sacc[nt][1] = sacc[nt][2] = sacc[nt][3] = 0.f;
            }
#pragma unroll
            for (int kk = 0; kk < 8; kk++) {
                const int d0 = kk * 8 + tig;
                uint32_t a[4];
                a[0] = __float_as_uint(qg[(size_t)d0 * HW + r0 + gid]);
                a[1] = __float_as_uint(qg[(size_t)d0 * HW + r0 + gid + 8]);
                a[2] = __float_as_uint(qg[(size_t)(d0 + 4) * HW + r0 + gid]);
                a[3] = __float_as_uint(qg[(size_t)(d0 + 4) * HW + r0 + gid + 8]);
#pragma unroll
                for (int nt = 0; nt < 13; nt++) {
                    uint32_t bfr[2];
                    bfr[0] = __float_as_uint(ksm[(nt * 8 + gid) * KST + d0]);
                    bfr[1] = __float_as_uint(ksm[(nt * 8 + gid) * KST + d0 + 4]);
                    mma_tf32(sacc[nt], a, bfr);
                }
            }
            mlo = -1e30f; mhi = -1e30f;
#pragma unroll
            for (int nt = 0; nt < 13; nt++) {
                mlo = fmaxf(mlo, fmaxf(sacc[nt][0], sacc[nt][1]));
                mhi = fmaxf(mhi, fmaxf(sacc[nt][2], sacc[nt][3]));
            }
            mlo = fmaxf(mlo, __shfl_xor_sync(0xffffffffu, mlo, 1));
            mlo = fmaxf(mlo, __shfl_xor_sync(0xffffffffu, mlo, 2));
            mhi = fmaxf(mhi, __shfl_xor_sync(0xffffffffu, mhi, 1));
            mhi = fmaxf(mhi, __shfl_xor_sync(0xffffffffu, mhi, 2));
            const float mls = mlo * ATTN_SCALE, mhs = mhi * ATTN_SCALE;
            llo = 0.f; lhi = 0.f;
#pragma unroll
            for (int nt = 0; nt < 13; nt++) {
                float e0 = __expf(fmaf(sacc[nt][0], ATTN_SCALE, -mls));
                float e1 = __expf(fmaf(sacc[nt][1], ATTN_SCALE, -mls));
                float e2 = __expf(fmaf(sacc[nt][2], ATTN_SCALE, -mhs));
                float e3 = __expf(fmaf(sacc[nt][3], ATTN_SCALE, -mhs));
                sacc[nt][0] = e0; sacc[nt][1] = e1; sacc[nt][2] = e2; sacc[nt][3] = e3;
                llo += e0 + e1; lhi += e2 + e3;
            }
            llo += __shfl_xor_sync(0xffffffffu, llo, 1);
            llo += __shfl_xor_sync(0xffffffffu, llo, 2);
            lhi += __shfl_xor_sync(0xffffffffu, lhi, 1);
            lhi += __shfl_xor_sync(0xffffffffu, lhi, 2);

#pragma unroll
            for (int kk = 0; kk < 13; kk++) {
                float u0 = __shfl_sync(0xffffffffu, sacc[kk][0], srcLow);
                float u1 = __shfl_sync(0xffffffffu, sacc[kk][1], srcLow);
                float w0 = __shfl_sync(0xffffffffu, sacc[kk][2], srcLow);
                float w1 = __shfl_sync(0xffffffffu, sacc[kk][3], srcLow);
                float v0 = __shfl_sync(0xffffffffu, sacc[kk][0], srcHigh);
                float v1 = __shfl_sync(0xffffffffu, sacc[kk][1], srcHigh);
                float z0 = __shfl_sync(0xffffffffu, sacc[kk][2], srcHigh);
                float z1 = __shfl_sync(0xffffffffu, sacc[kk][3], srcHigh);
                uint32_t a[4];
                a[0] = __float_as_uint(odd ? u1 : u0);
                a[1] = __float_as_uint(odd ? w1 : w0);
                a[2] = __float_as_uint(odd ? v1 : v0);
                a[3] = __float_as_uint(odd ? z1 : z0);
                const int j0 = kk * 8 + tig;
#pragma unroll
                for (int nt = 0; nt < 8; nt++) {
                    uint32_t bfr[2];
                    bfr[0] = __float_as_uint(vsm[j0 * VST + nt * 8 + gid]);
                    bfr[1] = __float_as_uint(vsm[(j0 + 4) * VST + nt * 8 + gid]);
                    mma_tf32(oacc[nt], a, bfr);
                }
            }
        }

        // ================= half 1: key tiles 13..24 ======
        {
            float sacc[12][4];
#pragma unroll
            for (int nt = 0; nt < 12; nt++) {
                sacc[nt][0] = sacc[nt][1] = sacc[nt][2] = sacc[nt][3] = 0.f;
            }
#pragma unroll
            for (int kk = 0; kk < 8; kk++) {
                const int d0 = kk * 8 + tig;
                uint32_t a[4];
                a[0] = __float_as_uint(qg[(size_t)d0 * HW + r0 + gid]);
                a[1] = __float_as_uint(qg[(size_t)d0 * HW + r0 + gid + 8]);
                a[2] = __float_as_uint(qg[(size_t)(d0 + 4) * HW + r0 + gid]);
                a[3] = __float_as_uint(qg[(size_t)(d0 + 4) * HW + r0 + gid + 8]);
#pragma unroll
                for (int nt = 0; nt < 12; nt++) {
                    uint32_t bfr[2];
                    bfr[0] = __float_as_uint(ksm[((13 + nt) * 8 + gid) * KST + d0]);
                    bfr[1] = __float_as_uint(ksm[((13 + nt) * 8 + gid) * KST + d0 + 4]);
                    mma_tf32(sacc[nt], a, bfr);
                }
            }
            if (tig >= 2) {
                sacc[11][0] = sacc[11][1] = sacc[11][2] = sacc[11][3] = -1e30f;
            }

            float m1lo = -1e30f, m1hi = -1e30f;
#pragma unroll
            for (int nt = 0; nt < 12; nt++) {
                m1lo = fmaxf(m1lo, fmaxf(sacc[nt][0], sacc[nt][1]));
                m1hi = fmaxf(m1hi, fmaxf(sacc[nt][2], sacc[nt][3]));
            }
            m1lo = fmaxf(m1lo, __shfl_xor_sync(0xffffffffu, m1lo, 1));
            m1lo = fmaxf(m1lo, __shfl_xor_sync(0xffffffffu, m1lo, 2));
            m1hi = fmaxf(m1hi, __shfl_xor_sync(0xffffffffu, m1hi, 1));
            m1hi = fmaxf(m1hi, __shfl_xor_sync(0xffffffffu, m1hi, 2));
            const float nmlo = fmaxf(mlo, m1lo), nmhi = fmaxf(mhi, m1hi);
            const float clo = __expf((mlo - nmlo) * ATTN_SCALE);
            const float chi = __expf((mhi - nmhi) * ATTN_SCALE);
            const float mls = nmlo * ATTN_SCALE, mhs = nmhi * ATTN_SCALE;
            float s1lo = 0.f, s1hi = 0.f;
#pragma unroll
            for (int nt = 0; nt < 12; nt++) {
                float e0 = __expf(fmaf(sacc[nt][0], ATTN_SCALE, -mls));
                float e1 = __expf(fmaf(sacc[nt][1], ATTN_SCALE, -mls));
                float e2 = __expf(fmaf(sacc[nt][2], ATTN_SCALE, -mhs));
                float e3 = __expf(fmaf(sacc[nt][3], ATTN_SCALE, -mhs));
                sacc[nt][0] = e0; sacc[nt][1] = e1; sacc[nt][2] = e2; sacc[nt][3] = e3;
                s1lo += e0 + e1; s1hi += e2 + e3;
            }
            s1lo += __shfl_xor_sync(0xffffffffu, s1lo, 1);
            s1lo += __shfl_xor_sync(0xffffffffu, s1lo, 2);
            s1hi += __shfl_xor_sync(0xffffffffu, s1hi, 1);
            s1hi += __shfl_xor_sync(0xffffffffu, s1hi, 2);
            llo = llo * clo + s1lo;
            lhi = lhi * chi + s1hi;
#pragma unroll
            for (int nt = 0; nt < 8; nt++) {
                oacc[nt][0] *= clo; oacc[nt][1] *= clo;
                oacc[nt][2] *= chi; oacc[nt][3] *= chi;
            }

#pragma unroll
            for (int kk = 0; kk < 12; kk++) {
                float u0 = __shfl_sync(0xffffffffu, sacc[kk][0], srcLow);
                float u1 = __shfl_sync(0xffffffffu, sacc[kk][1], srcLow);
                float w0 = __shfl_sync(0xffffffffu, sacc[kk][2], srcLow);
                float w1 = __shfl_sync(0xffffffffu, sacc[kk][3], srcLow);
                float v0 = __shfl_sync(0xffffffffu, sacc[kk][0], srcHigh);
                float v1 = __shfl_sync(0xffffffffu, sacc[kk][1], srcHigh);
                float z0 = __shfl_sync(0xffffffffu, sacc[kk][2], srcHigh);
                float z1 = __shfl_sync(0xffffffffu, sacc[kk][3], srcHigh);
                uint32_t a[4];
                a[0] = __float_as_uint(odd ? u1 : u0);
                a[1] = __float_as_uint(odd ? w1 : w0);
                a[2] = __float_as_uint(odd ? v1 : v0);
                a[3] = __float_as_uint(odd ? z1 : z0);
                const int j0 = (13 + kk) * 8 + tig;
#pragma unroll
                for (int nt = 0; nt < 8; nt++) {
                    uint32_t bfr[2];
                    bfr[0] = __float_as_uint(vsm[j0 * VST + nt * 8 + gid]);
                    bfr[1] = __float_as_uint(vsm[(j0 + 4) * VST + nt * 8 + gid]);
                    mma_tf32(oacc[nt], a, bfr);
                }
            }
        }

        // ---- epilogue: normalize + residual + LayerNorm + pool ----
        const float rlo2 = 1.f / llo, rhi2 = 1.f / lhi;
        float vlo[16], vhi[16];
        float slo2 = 0.f, shi2 = 0.f;
#pragma unroll
        for (int nt = 0; nt < 8; nt++)
#pragma unroll
            for (int c = 0; c < 2; c++) {
                const int i = nt * 2 + c;
                const int d = nt * 8 + 2 * tig + c;
                vlo[i] = oacc[nt][c]     * rlo2 + rg[(size_t)d * HW + r0 + gid];
                vhi[i] = oacc[nt][2 + c] * rhi2 + rg[(size_t)d * HW + r0 + gid + 8];
                slo2 += vlo[i]; shi2 += vhi[i];
            }
        slo2 += __shfl_xor_sync(0xffffffffu, slo2, 1);
        slo2 += __shfl_xor_sync(0xffffffffu, slo2, 2);
        shi2 += __shfl_xor_sync(0xffffffffu, shi2, 1);
        shi2 += __shfl_xor_sync(0xffffffffu, shi2, 2);
        const float mlo2 = slo2 * (1.f / 64.f), mhi2 = shi2 * (1.f / 64.f);
        float qlo = 0.f, qhi = 0.f;
#pragma unroll
        for (int i = 0; i < 16; i++) {
            float t1 = vlo[i] - mlo2; qlo += t1 * t1;
            float t2 = vhi[i] - mhi2; qhi += t2 * t2;
        }
        qlo += __shfl_xor_sync(0xffffffffu, qlo, 1);
        qlo += __shfl_xor_sync(0xffffffffu, qlo, 2);
        qhi += __shfl_xor_sync(0xffffffffu, qhi, 1);
        qhi += __shfl_xor_sync(0xffffffffu, qhi, 2);
        const float ilo = 1.f / (sqrtf(qlo * (1.f / 64.f)) + EPSF);
        const float ihi = 1.f / (sqrtf(qhi * (1.f / 64.f)) + EPSF);
#pragma unroll
        for (int nt = 0; nt < 8; nt++)
#pragma unroll
            for (int c = 0; c < 2; c++) {
                const int i = nt * 2 + c;
                const int d = nt * 8 + 2 * tig + c;
                const float lg = lnsm[d], lb = lnsm[64 + d];
                pacc[i] += (vlo[i] - mlo2) * ilo * lg + lb
                         + (vhi[i] - mhi2) * ihi * lg + lb;
            }
    }

#pragma unroll
    for (int i = 0; i < 16; i++) {
        pacc[i] += __shfl_xor_sync(0xffffffffu, pacc[i], 4);
        pacc[i] += __shfl_xor_sync(0xffffffffu, pacc[i], 8);
        pacc[i] += __shfl_xor_sync(0xffffffffu, pacc[i], 16);
    }
    if (gid == 0) {
#pragma unroll
        for (int nt = 0; nt < 8; nt++)
#pragma unroll
            for (int c = 0; c < 2; c++) {
                const int d = nt * 8 + 2 * tig + c;
                pool[warp * 64 + d] = pacc[nt * 2 + c];
            }
    }
    __syncthreads();
    if (tid < 64) {
        float s = 0.f;
#pragma unroll
        for (int w = 0; w < 8; w++) s += pool[w * 64 + tid];
        out[(size_t)bh * 64 + tid] = s * (1.f / 784.f);
    }
}

// =====================================================================
extern "C" void kernel_launch(void* const* d_in, const int* in_sizes, int n_in,
                              void* d_out, int out_size)
{
    const float* x      = (const float*)d_in[0];
    const float* w_dwq  = (const float*)d_in[1];
    const float* w_pwq  = (const float*)d_in[2];
    const float* w_dwkv = (const float*)d_in[3];
    const float* w_pwkv = (const float*)d_in[4];
    const float* w_ds   = (const float*)d_in[5];
    const float* ln_g   = (const float*)d_in[6];
    const float* ln_b   = (const float*)d_in[7];
    const float* bnq_g  = (const float*)d_in[8];
    const float* bnq_b  = (const float*)d_in[9];
    const float* bnq_m  = (const float*)d_in[10];
    const float* bnq_v  = (const float*)d_in[11];
    const float* bnkv_g = (const float*)d_in[12];
    const float* bnkv_b = (const float*)d_in[13];
    const float* bnkv_m = (const float*)d_in[14];
    const float* bnkv_v = (const float*)d_in[15];
    const float* bnds_g = (const float*)d_in[16];
    const float* bnds_b = (const float*)d_in[17];
    const float* bnds_m = (const float*)d_in[18];
    const float* bnds_v = (const float*)d_in[19];
    float* out = (float*)d_out;

    float *p_dwq, *p_dwkv, *p_q, *p_kv, *p_res, *p_wq, *p_wkv, *p_wds;
    cudaGetSymbolAddress((void**)&p_dwq,  g_dwq);
    cudaGetSymbolAddress((void**)&p_dwkv, g_dwkv);
    cudaGetSymbolAddress((void**)&p_q,    g_q);
    cudaGetSymbolAddress((void**)&p_kv,   g_kv);
    cudaGetSymbolAddress((void**)&p_res,  g_res);
    cudaGetSymbolAddress((void**)&p_wq,   g_wq);
    cudaGetSymbolAddress((void**)&p_wkv,  g_wkv);
    cudaGetSymbolAddress((void**)&p_wds,  g_wds);

    const int attn_smem = (200 * KST + 200 * VST + 512 + 128) * (int)sizeof(float); // 114560
    const int gemm_smem = GEMM_SMEM_FLOATS * (int)sizeof(float);                    // 53248

    static cudaStream_t s_side = nullptr;
    static cudaEvent_t ev_fork = nullptr, ev_prep = nullptr, ev_res = nullptr, ev_join = nullptr;
    if (s_side == nullptr) {
        cudaStreamCreateWithFlags(&s_side, cudaStreamNonBlocking);
        cudaEventCreateWithFlags(&ev_fork, cudaEventDisableTiming);
        cudaEventCreateWithFlags(&ev_prep, cudaEventDisableTiming);
        cudaEventCreateWithFlags(&ev_res,  cudaEventDisableTiming);
        cudaEventCreateWithFlags(&ev_join, cudaEventDisableTiming);
        cudaFuncSetAttribute(attn_tc,
                             cudaFuncAttributeMaxDynamicSharedMemorySize, attn_smem);
        cudaFuncSetAttribute(gemm_tc,
                             cudaFuncAttributeMaxDynamicSharedMemorySize, gemm_smem);
    }

    const int HB = NB / 2;  // 32 batches per pipeline chain

    // per-chain pointer offsets (chain 1)
    const float* x1      = x      + (size_t)HB * NC * HW;
    float*       p_dwq1  = p_dwq  + (size_t)HB * NC * HW;
    float*       p_dwkv1 = p_dwkv + (size_t)HB * NC * S2;
    float*       p_q1    = p_q    + (size_t)HB * INNER * HW;
    float*       p_kv1   = p_kv   + (size_t)HB * 2 * INNER * S2;
    float*       p_res1  = p_res  + (size_t)HB * DH * HW;

    // ---- fork side stream
    cudaEventRecord(ev_fork, 0);
    cudaStreamWaitEvent(s_side, ev_fork, 0);

    // side chain: prep -> ev_prep -> res(all) -> ev_res -> dw1 -> q1 -> kv1 -> attn1
    const int prep_total = PREP_Q_SZ + PREP_KV_SZ + PREP_DS_SZ;
    prep_all<<<(prep_total + 255) / 256, 256, 0, s_side>>>(w_pwq, w_pwkv, w_ds);
    cudaEventRecord(ev_prep, s_side);
    gemm_tc<<<dim3(13, 1, NB), 256, gemm_smem, s_side>>>(p_wds, x, p_res, 128, DH, HW, 0,
                                                         bnds_g, bnds_b, bnds_m, bnds_v);
    cudaEventRecord(ev_res, s_side);
    dwconv_fused<<<HB * NC, 256, 0, s_side>>>(x, w_dwq, w_dwkv,
                                              bnq_g, bnq_b, bnq_m, bnq_v,
                                              bnkv_g, bnkv_b, bnkv_m, bnkv_v,
                                              HB * NC);
    gemm_tc<<<dim3(13, 4, HB), 256, gemm_smem, s_side>>>(p_wq, p_dwq1, p_q1, 512, INNER, HW, 1,
                                                         nullptr, nullptr, nullptr, nullptr);
    gemm_tc<<<dim3(4, 8, HB), 256, gemm_smem, s_side>>>(p_wkv, p_dwkv1, p_kv1, 1024, 2 * INNER, S2, 1,
                                                        nullptr, nullptr, nullptr, nullptr);
    attn_tc<<<HB * NHEADS, 256, attn_smem, s_side>>>(ln_g, ln_b, out, HB * NHEADS);
    cudaEventRecord(ev_join, s_side);

    // main chain: dw0 -> (wait prep) q0 -> kv0 -> (wait res) attn0
    dwconv_fused<<<HB * NC, 256>>>(x, w_dwq, w_dwkv,
                                   bnq_g, bnq_b, bnq_m, bnq_v,
                                   bnkv_g, bnkv_b, bnkv_m, bnkv_v,
                                   0);
    cudaStreamWaitEvent(0, ev_prep, 0);
    gemm_tc<<<dim3(13, 4, HB), 256, gemm_smem>>>(p_wq, p_dwq, p_q, 512, INNER, HW, 1,
                                                 nullptr, nullptr, nullptr, nullptr);
    gemm_tc<<<dim3(4, 8, HB), 256, gemm_smem>>>(p_wkv, p_dwkv, p_kv, 1024, 2 * INNER, S2, 1,
                                                nullptr, nullptr, nullptr, nullptr);
    cudaStreamWaitEvent(0, ev_res, 0);
    attn_tc<<<HB * NHEADS, 256, attn_smem>>>(ln_g, ln_b, out, 0);

    // join side chain into main before return
    cudaStreamWaitEvent(0, ev_join, 0);
}